// round 2
// baseline (speedup 1.0000x reference)
#include <cuda_runtime.h>
#include <math.h>

#define BATCH 32
#define SEQ 197
#define EMB 768
#define NHEAD 12
#define HDIM 64
#define QKV3 2304
#define MLPD 3072
#define NLAYER 12
#define ROWS (BATCH*SEQ)      /* 6304 */
#define BHEADS (BATCH*NHEAD)  /* 384  */
#define NPATCH 196

// ---------------- scratch (static device globals; no allocs allowed) --------
__device__ float g_x[ROWS*EMB];
__device__ float g_h[ROWS*EMB];
__device__ float g_qkv[ROWS*QKV3];
__device__ float g_attn[BHEADS*SEQ*SEQ];
__device__ float g_o[ROWS*EMB];
__device__ float g_mlp[ROWS*MLPD];
__device__ float g_cls[BATCH*EMB];

__device__ __forceinline__ float gelu_f(float x){
    float x3 = x*x*x;
    return 0.5f*x*(1.0f + tanhf(0.7978845608028654f*(x + 0.044715f*x3)));
}

// ---------------- generic SGEMM: C(MxN) = A(MxK) @ B(KxN), epilogues --------
// epi: 0 = store, 1 = +bias, 2 = gelu(+bias), 3 = C += acc, 4 = C += acc+bias
// Requires: N % 128 == 0, K % 16 == 0. M arbitrary (predicated).
__global__ __launch_bounds__(256,2) void sgemm128(
    const float* __restrict__ A, const float* __restrict__ Bw,
    float* __restrict__ C, const float* __restrict__ bias,
    int M, int N, int K, int epi)
{
    __shared__ float As[16][132];
    __shared__ float Bs[16][132];
    const int tid = threadIdx.x;
    const int rowBase = blockIdx.y * 128;
    const int colBase = blockIdx.x * 128;
    const int ty = tid >> 4, tx = tid & 15;

    float acc[2][2][4][4];
#pragma unroll
    for (int a=0;a<2;a++)
#pragma unroll
      for (int b=0;b<2;b++)
#pragma unroll
        for (int i=0;i<4;i++)
#pragma unroll
          for (int j=0;j<4;j++) acc[a][b][i][j]=0.f;

    for (int k0 = 0; k0 < K; k0 += 16) {
        // load A tile 128x16 (float4, row-predicated)
#pragma unroll
        for (int i=0;i<2;i++){
            int idx = tid + i*256;
            int r = idx >> 2;
            int c4 = (idx & 3) << 2;
            int gr = rowBase + r;
            float4 v = make_float4(0.f,0.f,0.f,0.f);
            if (gr < M) v = *(const float4*)(A + (size_t)gr*K + k0 + c4);
            As[c4+0][r]=v.x; As[c4+1][r]=v.y; As[c4+2][r]=v.z; As[c4+3][r]=v.w;
        }
        // load B tile 16x128 (float4, always in-bounds on N)
#pragma unroll
        for (int i=0;i<2;i++){
            int idx = tid + i*256;
            int r = idx >> 5;
            int c4 = (idx & 31) << 2;
            *(float4*)&Bs[r][c4] = *(const float4*)(Bw + (size_t)(k0+r)*N + colBase + c4);
        }
        __syncthreads();

#pragma unroll
        for (int k=0;k<16;k++){
            float av[2][4], bv[2][4];
            *(float4*)&av[0][0] = *(const float4*)&As[k][ty*4];
            *(float4*)&av[1][0] = *(const float4*)&As[k][ty*4 + 64];
            *(float4*)&bv[0][0] = *(const float4*)&Bs[k][tx*4];
            *(float4*)&bv[1][0] = *(const float4*)&Bs[k][tx*4 + 64];
#pragma unroll
            for (int a=0;a<2;a++)
#pragma unroll
              for (int i=0;i<4;i++)
#pragma unroll
                for (int b=0;b<2;b++)
#pragma unroll
                  for (int j=0;j<4;j++)
                    acc[a][b][i][j] += av[a][i]*bv[b][j];
        }
        __syncthreads();
    }

    // epilogue
#pragma unroll
    for (int a=0;a<2;a++){
#pragma unroll
        for (int b=0;b<2;b++){
            int r0 = rowBase + ty*4 + a*64;
            int c0 = colBase + tx*4 + b*64;
#pragma unroll
            for (int i=0;i<4;i++){
                int r = r0 + i;
                if (r >= M) continue;
                float* Crow = C + (size_t)r*N + c0;
#pragma unroll
                for (int j=0;j<4;j++){
                    float v = acc[a][b][i][j];
                    if (epi == 0)      Crow[j] = v;
                    else if (epi == 1) Crow[j] = v + bias[c0+j];
                    else if (epi == 2) Crow[j] = gelu_f(v + bias[c0+j]);
                    else if (epi == 3) Crow[j] += v;
                    else               Crow[j] += v + bias[c0+j];
                }
            }
        }
    }
}

// ---------------- patch-embed GEMM: gathers patches from img on the fly ----
// A logical: (6272 x 768), A[m][k] = img[b][c][pr*16+py][pc*16+px]
// writes x[b*197+1+n][col] = acc + patch_b[col] + pos_emb[(1+n)*768+col]
__global__ __launch_bounds__(256,2) void patch_gemm(
    const float* __restrict__ img, const float* __restrict__ Bw,
    const float* __restrict__ pbias, const float* __restrict__ pos,
    float* __restrict__ X)
{
    __shared__ float As[16][132];
    __shared__ float Bs[16][132];
    const int tid = threadIdx.x;
    const int rowBase = blockIdx.y * 128;   // < 6272, exact tiles
    const int colBase = blockIdx.x * 128;
    const int ty = tid >> 4, tx = tid & 15;

    float acc[2][2][4][4];
#pragma unroll
    for (int a=0;a<2;a++)
#pragma unroll
      for (int b=0;b<2;b++)
#pragma unroll
        for (int i=0;i<4;i++)
#pragma unroll
          for (int j=0;j<4;j++) acc[a][b][i][j]=0.f;

    for (int k0 = 0; k0 < EMB; k0 += 16) {
#pragma unroll
        for (int i=0;i<2;i++){
            int idx = tid + i*256;
            int r = idx >> 2;
            int c4 = (idx & 3) << 2;
            int gr = rowBase + r;
            int gk = k0 + c4;
            int b  = gr / NPATCH;
            int n  = gr - b*NPATCH;
            int pr = n / 14, pc = n - pr*14;
            int ch = gk >> 8;
            int py = (gk >> 4) & 15;
            int px = gk & 15;
            const float* src = img + ((((size_t)(b*3+ch))*224 + pr*16+py)*224 + pc*16 + px);
            float4 v = *(const float4*)src;
            As[c4+0][r]=v.x; As[c4+1][r]=v.y; As[c4+2][r]=v.z; As[c4+3][r]=v.w;
        }
#pragma unroll
        for (int i=0;i<2;i++){
            int idx = tid + i*256;
            int r = idx >> 5;
            int c4 = (idx & 31) << 2;
            *(float4*)&Bs[r][c4] = *(const float4*)(Bw + (size_t)(k0+r)*EMB + colBase + c4);
        }
        __syncthreads();
#pragma unroll
        for (int k=0;k<16;k++){
            float av[2][4], bv[2][4];
            *(float4*)&av[0][0] = *(const float4*)&As[k][ty*4];
            *(float4*)&av[1][0] = *(const float4*)&As[k][ty*4 + 64];
            *(float4*)&bv[0][0] = *(const float4*)&Bs[k][tx*4];
            *(float4*)&bv[1][0] = *(const float4*)&Bs[k][tx*4 + 64];
#pragma unroll
            for (int a=0;a<2;a++)
#pragma unroll
              for (int i=0;i<4;i++)
#pragma unroll
                for (int b=0;b<2;b++)
#pragma unroll
                  for (int j=0;j<4;j++)
                    acc[a][b][i][j] += av[a][i]*bv[b][j];
        }
        __syncthreads();
    }

#pragma unroll
    for (int a=0;a<2;a++){
#pragma unroll
        for (int b=0;b<2;b++){
            int r0 = rowBase + ty*4 + a*64;
            int c0 = colBase + tx*4 + b*64;
#pragma unroll
            for (int i=0;i<4;i++){
                int r = r0 + i;   // always < 6272
                int bb = r / NPATCH;
                int n  = r - bb*NPATCH;
                float* Xrow = X + ((size_t)(bb*SEQ) + 1 + n)*EMB + c0;
                const float* prow = pos + (size_t)(1+n)*EMB + c0;
#pragma unroll
                for (int j=0;j<4;j++)
                    Xrow[j] = acc[a][b][i][j] + pbias[c0+j] + prow[j];
            }
        }
    }
}

// cls rows: x[b*197][e] = cls_token[e] + pos_emb[0][e]
__global__ void cls_init(const float* __restrict__ cls, const float* __restrict__ pos,
                         float* __restrict__ X)
{
    int idx = blockIdx.x*256 + threadIdx.x;   // 32*768 total
    if (idx >= BATCH*EMB) return;
    int b = idx / EMB, e = idx - b*EMB;
    X[(size_t)b*SEQ*EMB + e] = cls[e] + pos[e];
}

// ---------------- layernorm (no affine), one row per block ----------------
__global__ void ln_k(const float* __restrict__ in, float* __restrict__ out)
{
    int row = blockIdx.x;
    const float* p = in + (size_t)row*EMB;
    int t = threadIdx.x;
    float v[3]; float s=0.f, s2=0.f;
#pragma unroll
    for (int i=0;i<3;i++){ v[i]=p[t + i*256]; s+=v[i]; s2+=v[i]*v[i]; }
    __shared__ float sh[2][8];
#pragma unroll
    for (int o=16;o;o>>=1){ s += __shfl_xor_sync(0xffffffffu,s,o); s2 += __shfl_xor_sync(0xffffffffu,s2,o); }
    if ((t&31)==0){ sh[0][t>>5]=s; sh[1][t>>5]=s2; }
    __syncthreads();
    if (t < 32){
        s  = (t<8)? sh[0][t] : 0.f;
        s2 = (t<8)? sh[1][t] : 0.f;
#pragma unroll
        for (int o=4;o;o>>=1){ s += __shfl_xor_sync(0xffffffffu,s,o); s2 += __shfl_xor_sync(0xffffffffu,s2,o); }
        if (t==0){ sh[0][0]=s; sh[1][0]=s2; }
    }
    __syncthreads();
    float mu  = sh[0][0]*(1.f/EMB);
    float var = sh[1][0]*(1.f/EMB) - mu*mu;
    float inv = rsqrtf(var + 1e-5f);
    float* q = out + (size_t)row*EMB;
#pragma unroll
    for (int i=0;i<3;i++) q[t + i*256] = (v[i]-mu)*inv;
}

// final LN with gamma/beta on the 32 cls rows
__global__ void lnfinal_k(const float* __restrict__ X, const float* __restrict__ g,
                          const float* __restrict__ bta, float* __restrict__ out)
{
    int b = blockIdx.x;
    const float* p = X + (size_t)b*SEQ*EMB;
    int t = threadIdx.x;
    float v[3]; float s=0.f, s2=0.f;
#pragma unroll
    for (int i=0;i<3;i++){ v[i]=p[t + i*256]; s+=v[i]; s2+=v[i]*v[i]; }
    __shared__ float sh[2][8];
#pragma unroll
    for (int o=16;o;o>>=1){ s += __shfl_xor_sync(0xffffffffu,s,o); s2 += __shfl_xor_sync(0xffffffffu,s2,o); }
    if ((t&31)==0){ sh[0][t>>5]=s; sh[1][t>>5]=s2; }
    __syncthreads();
    if (t < 32){
        s  = (t<8)? sh[0][t] : 0.f;
        s2 = (t<8)? sh[1][t] : 0.f;
#pragma unroll
        for (int o=4;o;o>>=1){ s += __shfl_xor_sync(0xffffffffu,s,o); s2 += __shfl_xor_sync(0xffffffffu,s2,o); }
        if (t==0){ sh[0][0]=s; sh[1][0]=s2; }
    }
    __syncthreads();
    float mu  = sh[0][0]*(1.f/EMB);
    float var = sh[1][0]*(1.f/EMB) - mu*mu;
    float inv = rsqrtf(var + 1e-5f);
#pragma unroll
    for (int i=0;i<3;i++){
        int e = t + i*256;
        out[(size_t)b*EMB + e] = (v[i]-mu)*inv*g[e] + bta[e];
    }
}

// ---------------- attention scores: S = Q K^T / 8 ---------------------------
__global__ void attn_scores(const float* __restrict__ qkv, float* __restrict__ sc)
{
    int bh = blockIdx.z;
    int b = bh / NHEAD, h = bh - b*NHEAD;
    int q0 = blockIdx.y*16, k0 = blockIdx.x*16;
    __shared__ float Qs[16][65];
    __shared__ float Ks[16][65];
    int ty = threadIdx.y, tx = threadIdx.x;
    const float* base = qkv + (size_t)b*SEQ*QKV3 + h*HDIM;

    int qi = q0 + ty;
    float4 qa = make_float4(0,0,0,0);
    if (qi < SEQ) qa = *(const float4*)(base + (size_t)qi*QKV3 + tx*4);
    Qs[ty][tx*4+0]=qa.x; Qs[ty][tx*4+1]=qa.y; Qs[ty][tx*4+2]=qa.z; Qs[ty][tx*4+3]=qa.w;

    int ki = k0 + ty;
    float4 ka = make_float4(0,0,0,0);
    if (ki < SEQ) ka = *(const float4*)(base + EMB + (size_t)ki*QKV3 + tx*4);
    Ks[ty][tx*4+0]=ka.x; Ks[ty][tx*4+1]=ka.y; Ks[ty][tx*4+2]=ka.z; Ks[ty][tx*4+3]=ka.w;
    __syncthreads();

    int q = q0 + ty, k = k0 + tx;
    if (q < SEQ && k < SEQ) {
        float sum = 0.f;
#pragma unroll
        for (int d=0; d<HDIM; d++) sum += Qs[ty][d]*Ks[tx][d];
        sc[((size_t)bh*SEQ + q)*SEQ + k] = sum * 0.125f;
    }
}

// ---------------- softmax over rows of length 197 (one warp per row) --------
__global__ void softmax_k(float* __restrict__ sc)
{
    int warp = threadIdx.x >> 5;
    int lane = threadIdx.x & 31;
    int row = blockIdx.x*8 + warp;
    if (row >= BHEADS*SEQ) return;
    float* p = sc + (size_t)row*SEQ;
    float v[7]; float mx = -1e30f;
#pragma unroll
    for (int i=0;i<7;i++){
        int idx = lane + 32*i;
        v[i] = (idx < SEQ) ? p[idx] : -1e30f;
        mx = fmaxf(mx, v[i]);
    }
#pragma unroll
    for (int o=16;o;o>>=1) mx = fmaxf(mx, __shfl_xor_sync(0xffffffffu, mx, o));
    float sum = 0.f;
#pragma unroll
    for (int i=0;i<7;i++){ v[i] = expf(v[i]-mx); sum += v[i]; }
#pragma unroll
    for (int o=16;o;o>>=1) sum += __shfl_xor_sync(0xffffffffu, sum, o);
    float inv = 1.f/sum;
#pragma unroll
    for (int i=0;i<7;i++){
        int idx = lane + 32*i;
        if (idx < SEQ) p[idx] = v[i]*inv;
    }
}

// ---------------- O = attn @ V ----------------------------------------------
__global__ void attn_v(const float* __restrict__ sc, const float* __restrict__ qkv,
                       float* __restrict__ o)
{
    int bh = blockIdx.y;
    int b = bh / NHEAD, h = bh - b*NHEAD;
    int q0 = blockIdx.x*16;
    __shared__ float Ps[16][17];
    __shared__ float Vs[16][68];
    int ty = threadIdx.y, tx = threadIdx.x;
    float acc[4] = {0.f,0.f,0.f,0.f};
    const float* vbase = qkv + (size_t)b*SEQ*QKV3 + 2*EMB + h*HDIM;
    const float* abase = sc + (size_t)bh*SEQ*SEQ;

    for (int kt=0; kt<SEQ; kt+=16){
        float pv = 0.f;
        if (q0+ty < SEQ && kt+tx < SEQ) pv = abase[(size_t)(q0+ty)*SEQ + kt+tx];
        Ps[ty][tx] = pv;
        float4 vv = make_float4(0,0,0,0);
        if (kt+ty < SEQ) vv = *(const float4*)(vbase + (size_t)(kt+ty)*QKV3 + tx*4);
        *(float4*)&Vs[ty][tx*4] = vv;
        __syncthreads();
#pragma unroll
        for (int c=0;c<16;c++){
            float p = Ps[ty][c];
            float4 vr = *(const float4*)&Vs[c][tx*4];
            acc[0] += p*vr.x; acc[1] += p*vr.y; acc[2] += p*vr.z; acc[3] += p*vr.w;
        }
        __syncthreads();
    }
    int q = q0 + ty;
    if (q < SEQ){
        float* orow = o + ((size_t)b*SEQ + q)*EMB + h*HDIM + tx*4;
        orow[0]=acc[0]; orow[1]=acc[1]; orow[2]=acc[2]; orow[3]=acc[3];
    }
}

// ---------------- head: out(32x10) = cls(32x768) @ head_w + head_b ---------
__global__ void head_k(const float* __restrict__ cls, const float* __restrict__ hw,
                       const float* __restrict__ hb, float* __restrict__ out)
{
    int t = threadIdx.x;
    if (t >= BATCH*10) return;
    int b = t/10, c = t - b*10;
    float s = __ldg(hb + c);
    const float* crow = cls + (size_t)b*EMB;
    for (int e=0;e<EMB;e++) s += crow[e]*__ldg(hw + (size_t)e*10 + c);
    out[t] = s;
}

// ---------------- launch ----------------------------------------------------
extern "C" void kernel_launch(void* const* d_in, const int* in_sizes, int n_in,
                              void* d_out, int out_size)
{
    (void)in_sizes; (void)n_in; (void)out_size;
    const float* img     = (const float*)d_in[0];
    const float* patch_w = (const float*)d_in[1];
    const float* patch_b = (const float*)d_in[2];
    const float* cls_tok = (const float*)d_in[3];
    const float* pos_emb = (const float*)d_in[4];
    const float* qkv_w   = (const float*)d_in[5];
    const float* fc_w    = (const float*)d_in[6];
    const float* mlp_w1  = (const float*)d_in[7];
    const float* mlp_b1  = (const float*)d_in[8];
    const float* mlp_w2  = (const float*)d_in[9];
    const float* mlp_b2  = (const float*)d_in[10];
    const float* ln_g    = (const float*)d_in[11];
    const float* ln_b    = (const float*)d_in[12];
    const float* head_w  = (const float*)d_in[13];
    const float* head_b  = (const float*)d_in[14];
    float* out = (float*)d_out;

    static float *x=nullptr,*h=nullptr,*qkv=nullptr,*attn=nullptr,*o=nullptr,*mlp=nullptr,*clsb=nullptr;
    if (!x){
        cudaGetSymbolAddress((void**)&x,    g_x);
        cudaGetSymbolAddress((void**)&h,    g_h);
        cudaGetSymbolAddress((void**)&qkv,  g_qkv);
        cudaGetSymbolAddress((void**)&attn, g_attn);
        cudaGetSymbolAddress((void**)&o,    g_o);
        cudaGetSymbolAddress((void**)&mlp,  g_mlp);
        cudaGetSymbolAddress((void**)&clsb, g_cls);
    }

    // patch embed + positional
    patch_gemm<<<dim3(6,49),256>>>(img, patch_w, patch_b, pos_emb, x);
    cls_init<<<(BATCH*EMB+255)/256,256>>>(cls_tok, pos_emb, x);

    for (int l=0; l<NLAYER; l++){
        ln_k<<<ROWS,256>>>(x, h);
        sgemm128<<<dim3(QKV3/128,(ROWS+127)/128),256>>>(h, qkv_w + (size_t)l*EMB*QKV3, qkv, nullptr, ROWS, QKV3, EMB, 0);
        attn_scores<<<dim3((SEQ+15)/16,(SEQ+15)/16,BHEADS), dim3(16,16)>>>(qkv, attn);
        softmax_k<<<(BHEADS*SEQ+7)/8,256>>>(attn);
        attn_v<<<dim3((SEQ+15)/16,BHEADS), dim3(16,16)>>>(attn, qkv, o);
        sgemm128<<<dim3(EMB/128,(ROWS+127)/128),256>>>(o, fc_w + (size_t)l*EMB*EMB, x, nullptr, ROWS, EMB, EMB, 3);
        ln_k<<<ROWS,256>>>(x, h);
        sgemm128<<<dim3(MLPD/128,(ROWS+127)/128),256>>>(h, mlp_w1 + (size_t)l*EMB*MLPD, mlp, mlp_b1 + (size_t)l*MLPD, ROWS, MLPD, EMB, 2);
        sgemm128<<<dim3(EMB/128,(ROWS+127)/128),256>>>(mlp, mlp_w2 + (size_t)l*MLPD*EMB, x, mlp_b2 + (size_t)l*EMB, ROWS, EMB, MLPD, 4);
    }

    lnfinal_k<<<BATCH,256>>>(x, ln_g, ln_b, clsb);
    head_k<<<1,512>>>(clsb, head_w, head_b, out);
}

// round 5
// speedup vs baseline: 1.6406x; 1.6406x over previous
#include <cuda_runtime.h>
#include <cuda_bf16.h>
#include <math.h>
#include <stdint.h>

#define BATCH 32
#define SEQ 197
#define EMB 768
#define NHEAD 12
#define HDIM 64
#define QKV3 2304
#define MLPD 3072
#define NLAYER 12
#define ROWS (BATCH*SEQ)      /* 6304 */
#define ROWS_PAD 6400         /* 50*128 */
#define BHEADS (BATCH*NHEAD)  /* 384 */
#define NPATCH 196

// ---------------- scratch (static device globals) ---------------------------
__device__ float g_x[ROWS_PAD*EMB];
__device__ float g_qkv[ROWS_PAD*QKV3];
__device__ float g_attn[BHEADS*SEQ*SEQ];
__device__ float g_cls[BATCH*EMB];
__device__ __nv_bfloat16 g_hx3[(size_t)ROWS_PAD*QKV3];   // LN out, x3 split (K'=2304)
__device__ __nv_bfloat16 g_ox3[(size_t)ROWS_PAD*QKV3];   // attn out, x3 split
__device__ __nv_bfloat16 g_mx3[(size_t)ROWS_PAD*3*MLPD]; // mlp mid, x3 split (K'=9216)
__device__ __nv_bfloat16 g_wq[(size_t)NLAYER*QKV3*QKV3];  // qkv_w^T x3 (N=2304,K'=2304)
__device__ __nv_bfloat16 g_wf[(size_t)NLAYER*EMB*QKV3];   // fc_w^T  x3 (N=768, K'=2304)
__device__ __nv_bfloat16 g_w1[(size_t)NLAYER*MLPD*QKV3];  // w1^T    x3 (N=3072,K'=2304)
__device__ __nv_bfloat16 g_w2[(size_t)NLAYER*EMB*3*MLPD]; // w2^T    x3 (N=768, K'=9216)

__device__ __forceinline__ float gelu_f(float x){
    float x3 = x*x*x;
    return 0.5f*x*(1.0f + tanhf(0.7978845608028654f*(x + 0.044715f*x3)));
}

__device__ __forceinline__ uint32_t smem_u32(const void* p){
    uint32_t a;
    asm("{ .reg .u64 t; cvta.to.shared.u64 t, %1; cvt.u32.u64 %0, t; }" : "=r"(a) : "l"(p));
    return a;
}

#define LDSM4(r0,r1,r2,r3, addr) \
    asm volatile("ldmatrix.sync.aligned.m8n8.x4.shared.b16 {%0,%1,%2,%3}, [%4];" \
        : "=r"(r0),"=r"(r1),"=r"(r2),"=r"(r3) : "r"(addr))

#define MMA16816(d, a0,a1,a2,a3, b0,b1) \
    asm volatile("mma.sync.aligned.m16n8k16.row.col.f32.bf16.bf16.f32 " \
        "{%0,%1,%2,%3}, {%4,%5,%6,%7}, {%8,%9}, {%0,%1,%2,%3};" \
        : "+f"((d)[0]),"+f"((d)[1]),"+f"((d)[2]),"+f"((d)[3]) \
        : "r"(a0),"r"(a1),"r"(a2),"r"(a3), "r"(b0),"r"(b1))

// ---------------- tensor-core GEMM (mma.sync bf16) ---------------------------
// C_tile(128x128) = A'(rowBase.., K') x B't(colBase.., K')^T  over NC chunks of 64.
// A: (M_pad x ldk) bf16 row-major.  Bt: (N x ldk) bf16 row-major (= B^T).
// epi: 0 = fp32 store to outf (ld=ldo); 1 = outf += v (ld=768);
//      2 = gelu(v+bias) -> x3 into outx3 (seg=MLPD); 3 = outf += v + bias (ld=768)
#define SA0 0
#define SB0 16384
#define SA1 32768
#define SB1 49152
#define SM_TOTAL 65536

__global__ void __launch_bounds__(256) tgemm(
    const __nv_bfloat16* __restrict__ A, const __nv_bfloat16* __restrict__ Bt,
    int ldk, int NC,
    float* __restrict__ outf, int ldo, const float* __restrict__ bias,
    __nv_bfloat16* __restrict__ outx3, int epi)
{
    extern __shared__ char dsm[];
    const int tid = threadIdx.x;
    const int wid = tid >> 5;
    const int lane = tid & 31;
    const int warp_m = wid & 1;     // 2 x 64 rows
    const int warp_n = wid >> 1;    // 4 x 32 cols
    const int rowBase = blockIdx.y * 128;
    const int colBase = blockIdx.x * 128;
    const uint32_t sbase = smem_u32(dsm);

    const __nv_bfloat16* Ab = A  + (size_t)rowBase * ldk;
    const __nv_bfloat16* Bb = Bt + (size_t)colBase * ldk;

    float acc[4][4][4];
#pragma unroll
    for (int mt=0;mt<4;mt++)
#pragma unroll
      for (int nt=0;nt<4;nt++)
#pragma unroll
        for (int j=0;j<4;j++) acc[mt][nt][j]=0.f;

    // ldmatrix per-lane addressing components
    const int lA_row = warp_m*64 + (lane & 15);
    const int lA_kb  = (lane >> 4) * 16;
    const int g      = lane >> 3;
    const int lB_row = warp_n*32 + (lane & 7) + (g >> 1) * 8;
    const int lB_kb  = (g & 1) * 16;

    // loader mapping: idx -> (r 0..127, c 0..7), 8 bf16 per uint4
    const int ldr_r = tid >> 1;          // wait—recompute below per i
    (void)ldr_r;

    // preload chunk 0
#pragma unroll
    for (int i=0;i<4;i++){
        int idx = tid + i*256;
        int r = idx >> 3, c = idx & 7;
        uint4 va = *(const uint4*)(Ab + (size_t)r*ldk + c*8);
        uint4 vb = *(const uint4*)(Bb + (size_t)r*ldk + c*8);
        uint32_t off = r*128 + c*16;
        off ^= (off>>3)&0x70;
        *(uint4*)(dsm + SA0 + off) = va;
        *(uint4*)(dsm + SB0 + off) = vb;
    }
    __syncthreads();

    const uint32_t saoff[2] = {SA0, SA1};
    const uint32_t sboff[2] = {SB0, SB1};

    for (int c = 0; c < NC; c++){
        int cur = c & 1;
        uint4 pa[4], pb[4];
        bool pf = (c + 1 < NC);
        if (pf){
            int k0 = (c+1)*64;
#pragma unroll
            for (int i=0;i<4;i++){
                int idx = tid + i*256;
                int r = idx >> 3, cc = idx & 7;
                pa[i] = *(const uint4*)(Ab + (size_t)r*ldk + k0 + cc*8);
                pb[i] = *(const uint4*)(Bb + (size_t)r*ldk + k0 + cc*8);
            }
        }

        uint32_t sa = sbase + saoff[cur];
        uint32_t sb = sbase + sboff[cur];
#pragma unroll
        for (int ks=0; ks<4; ks++){
            uint32_t af[4][4], bf[2][4];
#pragma unroll
            for (int mt=0;mt<4;mt++){
                int row = lA_row + mt*16;
                uint32_t off = row*128 + ks*32 + lA_kb;
                off ^= (off>>3)&0x70;
                LDSM4(af[mt][0],af[mt][1],af[mt][2],af[mt][3], sa + off);
            }
#pragma unroll
            for (int bt=0;bt<2;bt++){
                int row = lB_row + bt*16;
                uint32_t off = row*128 + ks*32 + lB_kb;
                off ^= (off>>3)&0x70;
                LDSM4(bf[bt][0],bf[bt][1],bf[bt][2],bf[bt][3], sb + off);
            }
#pragma unroll
            for (int mt=0;mt<4;mt++)
#pragma unroll
              for (int nt=0;nt<4;nt++){
                  uint32_t b0 = bf[nt>>1][(nt&1)*2];
                  uint32_t b1 = bf[nt>>1][(nt&1)*2+1];
                  MMA16816(acc[mt][nt], af[mt][0],af[mt][1],af[mt][2],af[mt][3], b0,b1);
              }
        }

        if (pf){
            int nb = cur ^ 1;
#pragma unroll
            for (int i=0;i<4;i++){
                int idx = tid + i*256;
                int r = idx >> 3, cc = idx & 7;
                uint32_t off = r*128 + cc*16;
                off ^= (off>>3)&0x70;
                *(uint4*)(dsm + saoff[nb] + off) = pa[i];
                *(uint4*)(dsm + sboff[nb] + off) = pb[i];
            }
        }
        __syncthreads();
    }

    // epilogue straight from accumulators
    const int grp = lane >> 2;
    const int thc = (lane & 3) * 2;
#pragma unroll
    for (int mt=0;mt<4;mt++){
#pragma unroll
        for (int half=0; half<2; half++){
            int grow = rowBase + warp_m*64 + mt*16 + grp + half*8;
            if (grow >= ROWS) continue;
#pragma unroll
            for (int nt=0;nt<4;nt++){
                float v0 = acc[mt][nt][half*2+0];
                float v1 = acc[mt][nt][half*2+1];
                int gcol = colBase + warp_n*32 + nt*8 + thc;
                if (epi == 0){
                    float2* p = (float2*)(outf + (size_t)grow*ldo + gcol);
                    *p = make_float2(v0, v1);
                } else if (epi == 1){
                    float2* p = (float2*)(outf + (size_t)grow*EMB + gcol);
                    float2 x = *p;
                    x.x += v0; x.y += v1;
                    *p = x;
                } else if (epi == 2){
                    float t0 = gelu_f(v0 + bias[gcol]);
                    float t1 = gelu_f(v1 + bias[gcol+1]);
                    __nv_bfloat16 h0 = __float2bfloat16(t0);
                    __nv_bfloat16 l0 = __float2bfloat16(t0 - __bfloat162float(h0));
                    __nv_bfloat16 h1 = __float2bfloat16(t1);
                    __nv_bfloat16 l1 = __float2bfloat16(t1 - __bfloat162float(h1));
                    __nv_bfloat16* prow = outx3 + (size_t)grow*3*MLPD;
                    *(__nv_bfloat162*)(prow + gcol)            = __nv_bfloat162(h0,h1);
                    *(__nv_bfloat162*)(prow + MLPD + gcol)     = __nv_bfloat162(l0,l1);
                    *(__nv_bfloat162*)(prow + 2*MLPD + gcol)   = __nv_bfloat162(h0,h1);
                } else {
                    float2* p = (float2*)(outf + (size_t)grow*EMB + gcol);
                    float2 x = *p;
                    x.x += v0 + bias[gcol]; x.y += v1 + bias[gcol+1];
                    *p = x;
                }
            }
        }
    }
}

// ---------------- weight convert: (L,K,N) fp32 -> (L,N,3K) bf16 [hi|hi|lo] --
__global__ void wconv(const float* __restrict__ src, __nv_bfloat16* __restrict__ dst,
                      int K, int N)
{
    int l = blockIdx.z;
    src += (size_t)l*K*N;
    dst += (size_t)l*N*3*K;
    __shared__ float sm[32][33];
    int k0 = blockIdx.x*32, n0 = blockIdx.y*32;
#pragma unroll
    for (int i=0;i<4;i++){
        int k = k0 + threadIdx.y + i*8;
        sm[threadIdx.y + i*8][threadIdx.x] = src[(size_t)k*N + n0 + threadIdx.x];
    }
    __syncthreads();
#pragma unroll
    for (int i=0;i<4;i++){
        int n = n0 + threadIdx.y + i*8;
        int k = k0 + threadIdx.x;
        float v = sm[threadIdx.x][threadIdx.y + i*8];
        __nv_bfloat16 hi = __float2bfloat16(v);
        __nv_bfloat16 lo = __float2bfloat16(v - __bfloat162float(hi));
        __nv_bfloat16* drow = dst + (size_t)n*3*K;
        drow[k] = hi;
        drow[K + k] = hi;
        drow[2*K + k] = lo;
    }
}

// ---------------- patch-embed GEMM (fp32) -----------------------------------
__global__ __launch_bounds__(256,2) void patch_gemm(
    const float* __restrict__ img, const float* __restrict__ Bw,
    const float* __restrict__ pbias, const float* __restrict__ pos,
    float* __restrict__ X)
{
    __shared__ float As[16][132];
    __shared__ float Bs[16][132];
    const int tid = threadIdx.x;
    const int rowBase = blockIdx.y * 128;
    const int colBase = blockIdx.x * 128;
    const int ty = tid >> 4, tx = tid & 15;

    float acc[2][2][4][4];
#pragma unroll
    for (int a=0;a<2;a++)
#pragma unroll
      for (int b=0;b<2;b++)
#pragma unroll
        for (int i=0;i<4;i++)
#pragma unroll
          for (int j=0;j<4;j++) acc[a][b][i][j]=0.f;

    for (int k0 = 0; k0 < EMB; k0 += 16) {
#pragma unroll
        for (int i=0;i<2;i++){
            int idx = tid + i*256;
            int r = idx >> 2;
            int c4 = (idx & 3) << 2;
            int gr = rowBase + r;
            int gk = k0 + c4;
            int b  = gr / NPATCH;
            int n  = gr - b*NPATCH;
            int pr = n / 14, pc = n - pr*14;
            int ch = gk >> 8;
            int py = (gk >> 4) & 15;
            int px = gk & 15;
            const float* src = img + ((((size_t)(b*3+ch))*224 + pr*16+py)*224 + pc*16 + px);
            float4 v = *(const float4*)src;
            As[c4+0][r]=v.x; As[c4+1][r]=v.y; As[c4+2][r]=v.z; As[c4+3][r]=v.w;
        }
#pragma unroll
        for (int i=0;i<2;i++){
            int idx = tid + i*256;
            int r = idx >> 5;
            int c4 = (idx & 31) << 2;
            *(float4*)&Bs[r][c4] = *(const float4*)(Bw + (size_t)(k0+r)*EMB + colBase + c4);
        }
        __syncthreads();
#pragma unroll
        for (int k=0;k<16;k++){
            float av[2][4], bv[2][4];
            *(float4*)&av[0][0] = *(const float4*)&As[k][ty*4];
            *(float4*)&av[1][0] = *(const float4*)&As[k][ty*4 + 64];
            *(float4*)&bv[0][0] = *(const float4*)&Bs[k][tx*4];
            *(float4*)&bv[1][0] = *(const float4*)&Bs[k][tx*4 + 64];
#pragma unroll
            for (int a=0;a<2;a++)
#pragma unroll
              for (int i=0;i<4;i++)
#pragma unroll
                for (int b=0;b<2;b++)
#pragma unroll
                  for (int j=0;j<4;j++)
                    acc[a][b][i][j] += av[a][i]*bv[b][j];
        }
        __syncthreads();
    }

#pragma unroll
    for (int a=0;a<2;a++){
#pragma unroll
        for (int b=0;b<2;b++){
            int r0 = rowBase + ty*4 + a*64;
            int c0 = colBase + tx*4 + b*64;
#pragma unroll
            for (int i=0;i<4;i++){
                int r = r0 + i;
                int bb = r / NPATCH;
                int n  = r - bb*NPATCH;
                float* Xrow = X + ((size_t)(bb*SEQ) + 1 + n)*EMB + c0;
                const float* prow = pos + (size_t)(1+n)*EMB + c0;
#pragma unroll
                for (int j=0;j<4;j++)
                    Xrow[j] = acc[a][b][i][j] + pbias[c0+j] + prow[j];
            }
        }
    }
}

__global__ void cls_init(const float* __restrict__ cls, const float* __restrict__ pos,
                         float* __restrict__ X)
{
    int idx = blockIdx.x*256 + threadIdx.x;
    if (idx >= BATCH*EMB) return;
    int b = idx / EMB, e = idx - b*EMB;
    X[(size_t)b*SEQ*EMB + e] = cls[e] + pos[e];
}

// ---------------- layernorm -> bf16 x3 [hi|lo|hi] ---------------------------
__global__ void ln_x3(const float* __restrict__ in, __nv_bfloat16* __restrict__ out)
{
    int row = blockIdx.x;
    const float* p = in + (size_t)row*EMB;
    int t = threadIdx.x;
    float v[3]; float s=0.f, s2=0.f;
#pragma unroll
    for (int i=0;i<3;i++){ v[i]=p[t + i*256]; s+=v[i]; s2+=v[i]*v[i]; }
    __shared__ float sh[2][8];
#pragma unroll
    for (int o=16;o;o>>=1){ s += __shfl_xor_sync(0xffffffffu,s,o); s2 += __shfl_xor_sync(0xffffffffu,s2,o); }
    if ((t&31)==0){ sh[0][t>>5]=s; sh[1][t>>5]=s2; }
    __syncthreads();
    if (t < 32){
        s  = (t<8)? sh[0][t] : 0.f;
        s2 = (t<8)? sh[1][t] : 0.f;
#pragma unroll
        for (int o=4;o;o>>=1){ s += __shfl_xor_sync(0xffffffffu,s,o); s2 += __shfl_xor_sync(0xffffffffu,s2,o); }
        if (t==0){ sh[0][0]=s; sh[1][0]=s2; }
    }
    __syncthreads();
    float mu  = sh[0][0]*(1.f/EMB);
    float var = sh[1][0]*(1.f/EMB) - mu*mu;
    float inv = rsqrtf(var + 1e-5f);
    __nv_bfloat16* q = out + (size_t)row*QKV3;
#pragma unroll
    for (int i=0;i<3;i++){
        int e = t + i*256;
        float nv = (v[i]-mu)*inv;
        __nv_bfloat16 hi = __float2bfloat16(nv);
        __nv_bfloat16 lo = __float2bfloat16(nv - __bfloat162float(hi));
        q[e] = hi;
        q[EMB + e] = lo;
        q[2*EMB + e] = hi;
    }
}

__global__ void lnfinal_k(const float* __restrict__ X, const float* __restrict__ g,
                          const float* __restrict__ bta, float* __restrict__ out)
{
    int b = blockIdx.x;
    const float* p = X + (size_t)b*SEQ*EMB;
    int t = threadIdx.x;
    float v[3]; float s=0.f, s2=0.f;
#pragma unroll
    for (int i=0;i<3;i++){ v[i]=p[t + i*256]; s+=v[i]; s2+=v[i]*v[i]; }
    __shared__ float sh[2][8];
#pragma unroll
    for (int o=16;o;o>>=1){ s += __shfl_xor_sync(0xffffffffu,s,o); s2 += __shfl_xor_sync(0xffffffffu,s2,o); }
    if ((t&31)==0){ sh[0][t>>5]=s; sh[1][t>>5]=s2; }
    __syncthreads();
    if (t < 32){
        s  = (t<8)? sh[0][t] : 0.f;
        s2 = (t<8)? sh[1][t] : 0.f;
#pragma unroll
        for (int o=4;o;o>>=1){ s += __shfl_xor_sync(0xffffffffu,s,o); s2 += __shfl_xor_sync(0xffffffffu,s2,o); }
        if (t==0){ sh[0][0]=s; sh[1][0]=s2; }
    }
    __syncthreads();
    float mu  = sh[0][0]*(1.f/EMB);
    float var = sh[1][0]*(1.f/EMB) - mu*mu;
    float inv = rsqrtf(var + 1e-5f);
#pragma unroll
    for (int i=0;i<3;i++){
        int e = t + i*256;
        out[(size_t)b*EMB + e] = (v[i]-mu)*inv*g[e] + bta[e];
    }
}

// ---------------- attention scores: S = Q K^T / 8 ---------------------------
__global__ void attn_scores(const float* __restrict__ qkv, float* __restrict__ sc)
{
    int bh = blockIdx.z;
    int b = bh / NHEAD, h = bh - b*NHEAD;
    int q0 = blockIdx.y*16, k0 = blockIdx.x*16;
    __shared__ float Qs[16][65];
    __shared__ float Ks[16][65];
    int ty = threadIdx.y, tx = threadIdx.x;
    const float* base = qkv + (size_t)b*SEQ*QKV3 + h*HDIM;

    int qi = q0 + ty;
    float4 qa = make_float4(0,0,0,0);
    if (qi < SEQ) qa = *(const float4*)(base + (size_t)qi*QKV3 + tx*4);
    Qs[ty][tx*4+0]=qa.x; Qs[ty][tx*4+1]=qa.y; Qs[ty][tx*4+2]=qa.z; Qs[ty][tx*4+3]=qa.w;

    int ki = k0 + ty;
    float4 ka = make_float4(0,0,0,0);
    if (ki < SEQ) ka = *(const float4*)(base + EMB + (size_t)ki*QKV3 + tx*4);
    Ks[ty][tx*4+0]=ka.x; Ks[ty][tx*4+1]=ka.y; Ks[ty][tx*4+2]=ka.z; Ks[ty][tx*4+3]=ka.w;
    __syncthreads();

    int q = q0 + ty, k = k0 + tx;
    if (q < SEQ && k < SEQ) {
        float sum = 0.f;
#pragma unroll
        for (int d=0; d<HDIM; d++) sum += Qs[ty][d]*Ks[tx][d];
        sc[((size_t)bh*SEQ + q)*SEQ + k] = sum * 0.125f;
    }
}

__global__ void softmax_k(float* __restrict__ sc)
{
    int warp = threadIdx.x >> 5;
    int lane = threadIdx.x & 31;
    int row = blockIdx.x*8 + warp;
    if (row >= BHEADS*SEQ) return;
    float* p = sc + (size_t)row*SEQ;
    float v[7]; float mx = -1e30f;
#pragma unroll
    for (int i=0;i<7;i++){
        int idx = lane + 32*i;
        v[i] = (idx < SEQ) ? p[idx] : -1e30f;
        mx = fmaxf(mx, v[i]);
    }
#pragma unroll
    for (int o=16;o;o>>=1) mx = fmaxf(mx, __shfl_xor_sync(0xffffffffu, mx, o));
    float sum = 0.f;
#pragma unroll
    for (int i=0;i<7;i++){ v[i] = expf(v[i]-mx); sum += v[i]; }
#pragma unroll
    for (int o=16;o;o>>=1) sum += __shfl_xor_sync(0xffffffffu, sum, o);
    float inv = 1.f/sum;
#pragma unroll
    for (int i=0;i<7;i++){
        int idx = lane + 32*i;
        if (idx < SEQ) p[idx] = v[i]*inv;
    }
}

// ---------------- O = attn @ V, writes x3 -----------------------------------
__global__ void attn_v(const float* __restrict__ sc, const float* __restrict__ qkv,
                       __nv_bfloat16* __restrict__ ox3)
{
    int bh = blockIdx.y;
    int b = bh / NHEAD, h = bh - b*NHEAD;
    int q0 = blockIdx.x*16;
    __shared__ float Ps[16][17];
    __shared__ float Vs[16][68];
    int ty = threadIdx.y, tx = threadIdx.x;
    float acc[4] = {0.f,0.f,0.f,0.f};
    const float* vbase = qkv + (size_t)b*SEQ*QKV3 + 2*EMB + h*HDIM;
    const float* abase = sc + (size_t)bh*SEQ*SEQ;

    for (int kt=0; kt<SEQ; kt+=16){
        float pv = 0.f;
        if (q0+ty < SEQ && kt+tx < SEQ) pv = abase[(size_t)(q0+ty)*SEQ + kt+tx];
        Ps[ty][tx] = pv;
        float4 vv = make_float4(0,0,0,0);
        if (kt+ty < SEQ) vv = *(const float4*)(vbase + (size_t)(kt+ty)*QKV3 + tx*4);
        *(float4*)&Vs[ty][tx*4] = vv;
        __syncthreads();
#pragma unroll
        for (int c=0;c<16;c++){
            float p = Ps[ty][c];
            float4 vr = *(const float4*)&Vs[c][tx*4];
            acc[0] += p*vr.x; acc[1] += p*vr.y; acc[2] += p*vr.z; acc[3] += p*vr.w;
        }
        __syncthreads();
    }
    int q = q0 + ty;
    if (q < SEQ){
        size_t row = (size_t)b*SEQ + q;
        int col = h*HDIM + tx*4;
        __nv_bfloat16* orow = ox3 + row*QKV3;
#pragma unroll
        for (int j=0;j<4;j++){
            float v = acc[j];
            __nv_bfloat16 hi = __float2bfloat16(v);
            __nv_bfloat16 lo = __float2bfloat16(v - __bfloat162float(hi));
            orow[col+j] = hi;
            orow[EMB+col+j] = lo;
            orow[2*EMB+col+j] = hi;
        }
    }
}

__global__ void head_k(const float* __restrict__ cls, const float* __restrict__ hw,
                       const float* __restrict__ hb, float* __restrict__ out)
{
    int t = threadIdx.x;
    if (t >= BATCH*10) return;
    int b = t/10, c = t - b*10;
    float s = __ldg(hb + c);
    const float* crow = cls + (size_t)b*EMB;
    for (int e=0;e<EMB;e++) s += crow[e]*__ldg(hw + (size_t)e*10 + c);
    out[t] = s;
}

// ---------------- launch ----------------------------------------------------
extern "C" void kernel_launch(void* const* d_in, const int* in_sizes, int n_in,
                              void* d_out, int out_size)
{
    (void)in_sizes; (void)n_in; (void)out_size;
    const float* img     = (const float*)d_in[0];
    const float* patch_w = (const float*)d_in[1];
    const float* patch_b = (const float*)d_in[2];
    const float* cls_tok = (const float*)d_in[3];
    const float* pos_emb = (const float*)d_in[4];
    const float* qkv_w   = (const float*)d_in[5];
    const float* fc_w    = (const float*)d_in[6];
    const float* mlp_w1  = (const float*)d_in[7];
    const float* mlp_b1  = (const float*)d_in[8];
    const float* mlp_w2  = (const float*)d_in[9];
    const float* mlp_b2  = (const float*)d_in[10];
    const float* ln_g    = (const float*)d_in[11];
    const float* ln_b    = (const float*)d_in[12];
    const float* head_w  = (const float*)d_in[13];
    const float* head_b  = (const float*)d_in[14];
    float* out = (float*)d_out;

    static float *x=nullptr,*qkv=nullptr,*attn=nullptr,*clsb=nullptr;
    static __nv_bfloat16 *hx3=nullptr,*ox3=nullptr,*mx3=nullptr,*wq=nullptr,*wf=nullptr,*w1=nullptr,*w2=nullptr;
    if (!x){
        cudaGetSymbolAddress((void**)&x,    g_x);
        cudaGetSymbolAddress((void**)&qkv,  g_qkv);
        cudaGetSymbolAddress((void**)&attn, g_attn);
        cudaGetSymbolAddress((void**)&clsb, g_cls);
        cudaGetSymbolAddress((void**)&hx3,  g_hx3);
        cudaGetSymbolAddress((void**)&ox3,  g_ox3);
        cudaGetSymbolAddress((void**)&mx3,  g_mx3);
        cudaGetSymbolAddress((void**)&wq,   g_wq);
        cudaGetSymbolAddress((void**)&wf,   g_wf);
        cudaGetSymbolAddress((void**)&w1,   g_w1);
        cudaGetSymbolAddress((void**)&w2,   g_w2);
        cudaFuncSetAttribute(tgemm, cudaFuncAttributeMaxDynamicSharedMemorySize, SM_TOTAL);
    }

    // weight split+transpose (bf16 x3), all layers
    wconv<<<dim3(EMB/32,  QKV3/32, NLAYER), dim3(32,8)>>>(qkv_w,  wq, EMB,  QKV3);
    wconv<<<dim3(EMB/32,  EMB/32,  NLAYER), dim3(32,8)>>>(fc_w,   wf, EMB,  EMB);
    wconv<<<dim3(EMB/32,  MLPD/32, NLAYER), dim3(32,8)>>>(mlp_w1, w1, EMB,  MLPD);
    wconv<<<dim3(MLPD/32, EMB/32,  NLAYER), dim3(32,8)>>>(mlp_w2, w2, MLPD, EMB);

    patch_gemm<<<dim3(6,49),256>>>(img, patch_w, patch_b, pos_emb, x);
    cls_init<<<(BATCH*EMB+255)/256,256>>>(cls_tok, pos_emb, x);

    for (int l=0; l<NLAYER; l++){
        ln_x3<<<ROWS,256>>>(x, hx3);
        tgemm<<<dim3(QKV3/128, ROWS_PAD/128), 256, SM_TOTAL>>>(
            hx3, wq + (size_t)l*QKV3*QKV3, QKV3, 36, qkv, QKV3, nullptr, nullptr, 0);
        attn_scores<<<dim3((SEQ+15)/16,(SEQ+15)/16,BHEADS), dim3(16,16)>>>(qkv, attn);
        softmax_k<<<(BHEADS*SEQ+7)/8,256>>>(attn);
        attn_v<<<dim3((SEQ+15)/16,BHEADS), dim3(16,16)>>>(attn, qkv, ox3);
        tgemm<<<dim3(EMB/128, ROWS_PAD/128), 256, SM_TOTAL>>>(
            ox3, wf + (size_t)l*EMB*QKV3, QKV3, 36, x, EMB, nullptr, nullptr, 1);
        ln_x3<<<ROWS,256>>>(x, hx3);
        tgemm<<<dim3(MLPD/128, ROWS_PAD/128), 256, SM_TOTAL>>>(
            hx3, w1 + (size_t)l*MLPD*QKV3, QKV3, 36, nullptr, 0,
            mlp_b1 + (size_t)l*MLPD, mx3, 2);
        tgemm<<<dim3(EMB/128, ROWS_PAD/128), 256, SM_TOTAL>>>(
            mx3, w2 + (size_t)l*EMB*3*MLPD, 3*MLPD, 144, x, EMB,
            mlp_b2 + (size_t)l*EMB, nullptr, 3);
    }

    lnfinal_k<<<BATCH,256>>>(x, ln_g, ln_b, clsb);
    head_k<<<1,512>>>(clsb, head_w, head_b, out);
}

// round 9
// speedup vs baseline: 2.0593x; 1.2552x over previous
#include <cuda_runtime.h>
#include <cuda_bf16.h>
#include <math.h>
#include <stdint.h>

#define BATCH 32
#define SEQ 197
#define EMB 768
#define NHEAD 12
#define HDIM 64
#define QKV3 2304
#define MLPD 3072
#define NLAYER 12
#define ROWS (BATCH*SEQ)      /* 6304 */
#define ROWS_PAD 6400         /* 50*128 */
#define BHEADS (BATCH*NHEAD)  /* 384 */
#define NPATCH 196

// ---------------- scratch (static device globals) ---------------------------
__device__ float g_x[ROWS_PAD*EMB];
__device__ float g_qkv[ROWS_PAD*QKV3];
__device__ float g_cls[BATCH*EMB];
__device__ __nv_bfloat16 g_hx3[(size_t)ROWS_PAD*QKV3];   // LN out, x3 split (K'=2304)
__device__ __nv_bfloat16 g_ox3[(size_t)ROWS_PAD*QKV3];   // attn out, x3 split
__device__ __nv_bfloat16 g_mx3[(size_t)ROWS_PAD*3*MLPD]; // mlp mid, x3 split (K'=9216)
__device__ __nv_bfloat16 g_wq[(size_t)NLAYER*QKV3*QKV3];  // qkv_w^T x3
__device__ __nv_bfloat16 g_wf[(size_t)NLAYER*EMB*QKV3];   // fc_w^T  x3
__device__ __nv_bfloat16 g_w1[(size_t)NLAYER*MLPD*QKV3];  // w1^T    x3
__device__ __nv_bfloat16 g_w2[(size_t)NLAYER*EMB*3*MLPD]; // w2^T    x3

__device__ __forceinline__ float gelu_f(float x){
    float x3 = x*x*x;
    return 0.5f*x*(1.0f + tanhf(0.7978845608028654f*(x + 0.044715f*x3)));
}

__device__ __forceinline__ uint32_t smem_u32(const void* p){
    uint32_t a;
    asm("{ .reg .u64 t; cvta.to.shared.u64 t, %1; cvt.u32.u64 %0, t; }" : "=r"(a) : "l"(p));
    return a;
}

#define LDSM4(r0,r1,r2,r3, addr) \
    asm volatile("ldmatrix.sync.aligned.m8n8.x4.shared.b16 {%0,%1,%2,%3}, [%4];" \
        : "=r"(r0),"=r"(r1),"=r"(r2),"=r"(r3) : "r"(addr))

#define MMA16816(d, a0,a1,a2,a3, b0,b1) \
    asm volatile("mma.sync.aligned.m16n8k16.row.col.f32.bf16.bf16.f32 " \
        "{%0,%1,%2,%3}, {%4,%5,%6,%7}, {%8,%9}, {%0,%1,%2,%3};" \
        : "+f"((d)[0]),"+f"((d)[1]),"+f"((d)[2]),"+f"((d)[3]) \
        : "r"(a0),"r"(a1),"r"(a2),"r"(a3), "r"(b0),"r"(b1))

// ---------------- tensor-core GEMM (mma.sync bf16) ---------------------------
#define SA0 0
#define SB0 16384
#define SA1 32768
#define SB1 49152
#define SM_TOTAL 65536

__global__ void __launch_bounds__(256) tgemm(
    const __nv_bfloat16* __restrict__ A, const __nv_bfloat16* __restrict__ Bt,
    int ldk, int NC,
    float* __restrict__ outf, int ldo, const float* __restrict__ bias,
    __nv_bfloat16* __restrict__ outx3, int epi)
{
    extern __shared__ char dsm[];
    const int tid = threadIdx.x;
    const int wid = tid >> 5;
    const int lane = tid & 31;
    const int warp_m = wid & 1;
    const int warp_n = wid >> 1;
    const int rowBase = blockIdx.y * 128;
    const int colBase = blockIdx.x * 128;
    const uint32_t sbase = smem_u32(dsm);

    const __nv_bfloat16* Ab = A  + (size_t)rowBase * ldk;
    const __nv_bfloat16* Bb = Bt + (size_t)colBase * ldk;

    float acc[4][4][4];
#pragma unroll
    for (int mt=0;mt<4;mt++)
#pragma unroll
      for (int nt=0;nt<4;nt++)
#pragma unroll
        for (int j=0;j<4;j++) acc[mt][nt][j]=0.f;

    const int lA_row = warp_m*64 + (lane & 15);
    const int lA_kb  = (lane >> 4) * 16;
    const int g      = lane >> 3;
    const int lB_row = warp_n*32 + (lane & 7) + (g >> 1) * 8;
    const int lB_kb  = (g & 1) * 16;

#pragma unroll
    for (int i=0;i<4;i++){
        int idx = tid + i*256;
        int r = idx >> 3, c = idx & 7;
        uint4 va = *(const uint4*)(Ab + (size_t)r*ldk + c*8);
        uint4 vb = *(const uint4*)(Bb + (size_t)r*ldk + c*8);
        uint32_t off = r*128 + c*16;
        off ^= (off>>3)&0x70;
        *(uint4*)(dsm + SA0 + off) = va;
        *(uint4*)(dsm + SB0 + off) = vb;
    }
    __syncthreads();

    const uint32_t saoff[2] = {SA0, SA1};
    const uint32_t sboff[2] = {SB0, SB1};

    for (int c = 0; c < NC; c++){
        int cur = c & 1;
        uint4 pa[4], pb[4];
        bool pf = (c + 1 < NC);
        if (pf){
            int k0 = (c+1)*64;
#pragma unroll
            for (int i=0;i<4;i++){
                int idx = tid + i*256;
                int r = idx >> 3, cc = idx & 7;
                pa[i] = *(const uint4*)(Ab + (size_t)r*ldk + k0 + cc*8);
                pb[i] = *(const uint4*)(Bb + (size_t)r*ldk + k0 + cc*8);
            }
        }

        uint32_t sa = sbase + saoff[cur];
        uint32_t sb = sbase + sboff[cur];
#pragma unroll
        for (int ks=0; ks<4; ks++){
            uint32_t af[4][4], bf[2][4];
#pragma unroll
            for (int mt=0;mt<4;mt++){
                int row = lA_row + mt*16;
                uint32_t off = row*128 + ks*32 + lA_kb;
                off ^= (off>>3)&0x70;
                LDSM4(af[mt][0],af[mt][1],af[mt][2],af[mt][3], sa + off);
            }
#pragma unroll
            for (int bt=0;bt<2;bt++){
                int row = lB_row + bt*16;
                uint32_t off = row*128 + ks*32 + lB_kb;
                off ^= (off>>3)&0x70;
                LDSM4(bf[bt][0],bf[bt][1],bf[bt][2],bf[bt][3], sb + off);
            }
#pragma unroll
            for (int mt=0;mt<4;mt++)
#pragma unroll
              for (int nt=0;nt<4;nt++){
                  uint32_t b0 = bf[nt>>1][(nt&1)*2];
                  uint32_t b1 = bf[nt>>1][(nt&1)*2+1];
                  MMA16816(acc[mt][nt], af[mt][0],af[mt][1],af[mt][2],af[mt][3], b0,b1);
              }
        }

        if (pf){
            int nb = cur ^ 1;
#pragma unroll
            for (int i=0;i<4;i++){
                int idx = tid + i*256;
                int r = idx >> 3, cc = idx & 7;
                uint32_t off = r*128 + cc*16;
                off ^= (off>>3)&0x70;
                *(uint4*)(dsm + saoff[nb] + off) = pa[i];
                *(uint4*)(dsm + sboff[nb] + off) = pb[i];
            }
        }
        __syncthreads();
    }

    const int grp = lane >> 2;
    const int thc = (lane & 3) * 2;
#pragma unroll
    for (int mt=0;mt<4;mt++){
#pragma unroll
        for (int half=0; half<2; half++){
            int grow = rowBase + warp_m*64 + mt*16 + grp + half*8;
            if (grow >= ROWS) continue;
#pragma unroll
            for (int nt=0;nt<4;nt++){
                float v0 = acc[mt][nt][half*2+0];
                float v1 = acc[mt][nt][half*2+1];
                int gcol = colBase + warp_n*32 + nt*8 + thc;
                if (epi == 0){
                    float2* p = (float2*)(outf + (size_t)grow*ldo + gcol);
                    *p = make_float2(v0, v1);
                } else if (epi == 1){
                    float2* p = (float2*)(outf + (size_t)grow*EMB + gcol);
                    float2 x = *p;
                    x.x += v0; x.y += v1;
                    *p = x;
                } else if (epi == 2){
                    float t0 = gelu_f(v0 + bias[gcol]);
                    float t1 = gelu_f(v1 + bias[gcol+1]);
                    __nv_bfloat16 h0 = __float2bfloat16(t0);
                    __nv_bfloat16 l0 = __float2bfloat16(t0 - __bfloat162float(h0));
                    __nv_bfloat16 h1 = __float2bfloat16(t1);
                    __nv_bfloat16 l1 = __float2bfloat16(t1 - __bfloat162float(h1));
                    __nv_bfloat16* prow = outx3 + (size_t)grow*3*MLPD;
                    *(__nv_bfloat162*)(prow + gcol)            = __nv_bfloat162(h0,h1);
                    *(__nv_bfloat162*)(prow + MLPD + gcol)     = __nv_bfloat162(l0,l1);
                    *(__nv_bfloat162*)(prow + 2*MLPD + gcol)   = __nv_bfloat162(h0,h1);
                } else {
                    float2* p = (float2*)(outf + (size_t)grow*EMB + gcol);
                    float2 x = *p;
                    x.x += v0 + bias[gcol]; x.y += v1 + bias[gcol+1];
                    *p = x;
                }
            }
        }
    }
}

// ---------------- fused attention, conservative SMEM (59.7 KB) --------------
// grid (7 qtiles of 32, BHEADS), block 256.
// Phase 1: Ks(197x65) + Qs(32x65) resident -> scores in regs.
// Phase 2 (after CTA barrier): Ps(32x200) aliased into Ks region;
//          V streamed in 32-row chunks (stride 66, 8B-aligned) thru Qs region.
#define FA_KS 0          /* K region: 197*65 = 12805 floats; later Ps (needs 6400) */
#define FA_QS 12806      /* EVEN base: Q (32*65=2080); later V chunk (32*66=2112) */
#define FA_FLOATS (FA_QS + 2112)   /* 14918 */
#define FA_SMEM (FA_FLOATS*4)      /* 59672 B < proven 65536 */

__global__ void __launch_bounds__(256) fattn(const float* __restrict__ qkv,
                                             __nv_bfloat16* __restrict__ ox3)
{
    extern __shared__ float fsm[];
    float* Ks = fsm + FA_KS;
    float* Qs = fsm + FA_QS;
    float* Ps = fsm + FA_KS;   // alias: valid after post-scores barrier (scalar access)
    float* Vs = fsm + FA_QS;   // alias: even base, stride 66 -> float2-aligned
    const int tid = threadIdx.x, wid = tid >> 5, lane = tid & 31;
    const int bh = blockIdx.y;
    const int b = bh / NHEAD, h = bh - b*NHEAD;
    const int q0 = blockIdx.x * 32;
    const float* base = qkv + (size_t)b*SEQ*QKV3 + h*HDIM;

    // load K (197x64) and Q tile (32x64), stride 65 (scalar stores)
    for (int idx = tid; idx < SEQ*16; idx += 256){
        int r = idx >> 4, c4 = (idx & 15) << 2;
        float4 v = *(const float4*)(base + EMB + (size_t)r*QKV3 + c4);
        float* d = Ks + r*65 + c4;
        d[0]=v.x; d[1]=v.y; d[2]=v.z; d[3]=v.w;
    }
    for (int idx = tid; idx < 32*16; idx += 256){
        int r = idx >> 4, c4 = (idx & 15) << 2;
        int qr = q0 + r;
        float4 v = make_float4(0.f,0.f,0.f,0.f);
        if (qr < SEQ) v = *(const float4*)(base + (size_t)qr*QKV3 + c4);
        float* d = Qs + r*65 + c4;
        d[0]=v.x; d[1]=v.y; d[2]=v.z; d[3]=v.w;
    }
    __syncthreads();

    // scores: warp owns rows wid*4..+3; lane owns keys lane+32*kk, kk<7
    float s[4][7];
#pragma unroll
    for (int r=0;r<4;r++)
#pragma unroll
      for (int kk=0;kk<7;kk++) s[r][kk]=0.f;

    for (int d0=0; d0<HDIM; d0+=4){
        float q[4][4], k[7][4];
#pragma unroll
        for (int r=0;r<4;r++){
            const float* qp = Qs + (wid*4+r)*65 + d0;
            q[r][0]=qp[0]; q[r][1]=qp[1]; q[r][2]=qp[2]; q[r][3]=qp[3];
        }
#pragma unroll
        for (int kk=0;kk<7;kk++){
            const float* kp = Ks + (lane+32*kk)*65 + d0;
            k[kk][0]=kp[0]; k[kk][1]=kp[1]; k[kk][2]=kp[2]; k[kk][3]=kp[3];
        }
#pragma unroll
        for (int r=0;r<4;r++)
#pragma unroll
          for (int kk=0;kk<7;kk++)
#pragma unroll
            for (int j=0;j<4;j++)
                s[r][kk] += q[r][j]*k[kk][j];
    }

    // softmax in registers (warp-local rows); keep unnormalized P + 1/sum
    float invs[4];
#pragma unroll
    for (int r=0;r<4;r++){
        float mx = -1e30f;
#pragma unroll
        for (int kk=0;kk<7;kk++){
            int key = lane + 32*kk;
            s[r][kk] = (key < SEQ) ? s[r][kk]*0.125f : -1e30f;
            mx = fmaxf(mx, s[r][kk]);
        }
#pragma unroll
        for (int o=16;o;o>>=1) mx = fmaxf(mx, __shfl_xor_sync(0xffffffffu, mx, o));
        float sum = 0.f;
#pragma unroll
        for (int kk=0;kk<7;kk++){
            float p = __expf(s[r][kk]-mx);
            s[r][kk] = p; sum += p;
        }
#pragma unroll
        for (int o=16;o;o>>=1) sum += __shfl_xor_sync(0xffffffffu, sum, o);
        invs[r] = 1.f/sum;
    }

    // retire all Ks/Qs reads before aliasing the buffers
    __syncthreads();

    // spill P into (dead) K region (scalar stores)
#pragma unroll
    for (int r=0;r<4;r++){
#pragma unroll
        for (int kk=0;kk<7;kk++){
            int key = lane + 32*kk;
            if (key < SEQ) Ps[(wid*4+r)*200 + key] = s[r][kk];
        }
    }

    // O = P @ V over V chunks of 32 rows streamed through (dead) Q region
    float o[4][2];
#pragma unroll
    for (int r=0;r<4;r++){ o[r][0]=0.f; o[r][1]=0.f; }

    for (int kt=0; kt<SEQ; kt+=32){
        int nrows = SEQ - kt; if (nrows > 32) nrows = 32;
        __syncthreads();   // prior chunk consumed (and Ps writes globally visible)
        for (int idx = tid; idx < nrows*16; idx += 256){
            int r = idx >> 4, c4 = (idx & 15) << 2;
            float4 v = *(const float4*)(base + 2*EMB + (size_t)(kt+r)*QKV3 + c4);
            float* d = Vs + r*66 + c4;
            d[0]=v.x; d[1]=v.y; d[2]=v.z; d[3]=v.w;
        }
        __syncthreads();
        for (int kl=0; kl<nrows; kl++){
            float2 vv = *(float2*)(Vs + kl*66 + lane*2);   // even base+stride: aligned
#pragma unroll
            for (int r=0;r<4;r++){
                float p = Ps[(wid*4+r)*200 + kt + kl];
                o[r][0] += p*vv.x; o[r][1] += p*vv.y;
            }
        }
    }

    // write x3 bf16
#pragma unroll
    for (int r=0;r<4;r++){
        int qr = q0 + wid*4 + r;
        if (qr >= SEQ) continue;
        float v0 = o[r][0]*invs[r], v1 = o[r][1]*invs[r];
        __nv_bfloat16 h0=__float2bfloat16(v0), l0=__float2bfloat16(v0-__bfloat162float(h0));
        __nv_bfloat16 h1=__float2bfloat16(v1), l1=__float2bfloat16(v1-__bfloat162float(h1));
        __nv_bfloat16* orow = ox3 + ((size_t)b*SEQ + qr)*QKV3;
        int col = h*HDIM + lane*2;
        *(__nv_bfloat162*)(orow + col)         = __nv_bfloat162(h0,h1);
        *(__nv_bfloat162*)(orow + EMB + col)   = __nv_bfloat162(l0,l1);
        *(__nv_bfloat162*)(orow + 2*EMB + col) = __nv_bfloat162(h0,h1);
    }
}

// ---------------- weight convert: (L,K,N) fp32 -> (L,N,3K) bf16 [hi|hi|lo] --
__global__ void wconv(const float* __restrict__ src, __nv_bfloat16* __restrict__ dst,
                      int K, int N)
{
    int l = blockIdx.z;
    src += (size_t)l*K*N;
    dst += (size_t)l*N*3*K;
    __shared__ float sm[32][33];
    int k0 = blockIdx.x*32, n0 = blockIdx.y*32;
#pragma unroll
    for (int i=0;i<4;i++){
        int k = k0 + threadIdx.y + i*8;
        sm[threadIdx.y + i*8][threadIdx.x] = src[(size_t)k*N + n0 + threadIdx.x];
    }
    __syncthreads();
#pragma unroll
    for (int i=0;i<4;i++){
        int n = n0 + threadIdx.y + i*8;
        int k = k0 + threadIdx.x;
        float v = sm[threadIdx.x][threadIdx.y + i*8];
        __nv_bfloat16 hi = __float2bfloat16(v);
        __nv_bfloat16 lo = __float2bfloat16(v - __bfloat162float(hi));
        __nv_bfloat16* drow = dst + (size_t)n*3*K;
        drow[k] = hi;
        drow[K + k] = hi;
        drow[2*K + k] = lo;
    }
}

// ---------------- patch-embed GEMM (fp32) -----------------------------------
__global__ __launch_bounds__(256,2) void patch_gemm(
    const float* __restrict__ img, const float* __restrict__ Bw,
    const float* __restrict__ pbias, const float* __restrict__ pos,
    float* __restrict__ X)
{
    __shared__ float As[16][132];
    __shared__ float Bs[16][132];
    const int tid = threadIdx.x;
    const int rowBase = blockIdx.y * 128;
    const int colBase = blockIdx.x * 128;
    const int ty = tid >> 4, tx = tid & 15;

    float acc[2][2][4][4];
#pragma unroll
    for (int a=0;a<2;a++)
#pragma unroll
      for (int b=0;b<2;b++)
#pragma unroll
        for (int i=0;i<4;i++)
#pragma unroll
          for (int j=0;j<4;j++) acc[a][b][i][j]=0.f;

    for (int k0 = 0; k0 < EMB; k0 += 16) {
#pragma unroll
        for (int i=0;i<2;i++){
            int idx = tid + i*256;
            int r = idx >> 2;
            int c4 = (idx & 3) << 2;
            int gr = rowBase + r;
            int gk = k0 + c4;
            int b  = gr / NPATCH;
            int n  = gr - b*NPATCH;
            int pr = n / 14, pc = n - pr*14;
            int ch = gk >> 8;
            int py = (gk >> 4) & 15;
            int px = gk & 15;
            const float* src = img + ((((size_t)(b*3+ch))*224 + pr*16+py)*224 + pc*16 + px);
            float4 v = *(const float4*)src;
            As[c4+0][r]=v.x; As[c4+1][r]=v.y; As[c4+2][r]=v.z; As[c4+3][r]=v.w;
        }
#pragma unroll
        for (int i=0;i<2;i++){
            int idx = tid + i*256;
            int r = idx >> 5;
            int c4 = (idx & 31) << 2;
            *(float4*)&Bs[r][c4] = *(const float4*)(Bw + (size_t)(k0+r)*EMB + colBase + c4);
        }
        __syncthreads();
#pragma unroll
        for (int k=0;k<16;k++){
            float av[2][4], bv[2][4];
            *(float4*)&av[0][0] = *(const float4*)&As[k][ty*4];
            *(float4*)&av[1][0] = *(const float4*)&As[k][ty*4 + 64];
            *(float4*)&bv[0][0] = *(const float4*)&Bs[k][tx*4];
            *(float4*)&bv[1][0] = *(const float4*)&Bs[k][tx*4 + 64];
#pragma unroll
            for (int a=0;a<2;a++)
#pragma unroll
              for (int i=0;i<4;i++)
#pragma unroll
                for (int b=0;b<2;b++)
#pragma unroll
                  for (int j=0;j<4;j++)
                    acc[a][b][i][j] += av[a][i]*bv[b][j];
        }
        __syncthreads();
    }

#pragma unroll
    for (int a=0;a<2;a++){
#pragma unroll
        for (int b=0;b<2;b++){
            int r0 = rowBase + ty*4 + a*64;
            int c0 = colBase + tx*4 + b*64;
#pragma unroll
            for (int i=0;i<4;i++){
                int r = r0 + i;
                int bb = r / NPATCH;
                int n  = r - bb*NPATCH;
                float* Xrow = X + ((size_t)(bb*SEQ) + 1 + n)*EMB + c0;
                const float* prow = pos + (size_t)(1+n)*EMB + c0;
#pragma unroll
                for (int j=0;j<4;j++)
                    Xrow[j] = acc[a][b][i][j] + pbias[c0+j] + prow[j];
            }
        }
    }
}

__global__ void cls_init(const float* __restrict__ cls, const float* __restrict__ pos,
                         float* __restrict__ X)
{
    int idx = blockIdx.x*256 + threadIdx.x;
    if (idx >= BATCH*EMB) return;
    int b = idx / EMB, e = idx - b*EMB;
    X[(size_t)b*SEQ*EMB + e] = cls[e] + pos[e];
}

// ---------------- layernorm -> bf16 x3 [hi|lo|hi] ---------------------------
__global__ void ln_x3(const float* __restrict__ in, __nv_bfloat16* __restrict__ out)
{
    int row = blockIdx.x;
    const float* p = in + (size_t)row*EMB;
    int t = threadIdx.x;
    float v[3]; float s=0.f, s2=0.f;
#pragma unroll
    for (int i=0;i<3;i++){ v[i]=p[t + i*256]; s+=v[i]; s2+=v[i]*v[i]; }
    __shared__ float sh[2][8];
#pragma unroll
    for (int o=16;o;o>>=1){ s += __shfl_xor_sync(0xffffffffu,s,o); s2 += __shfl_xor_sync(0xffffffffu,s2,o); }
    if ((t&31)==0){ sh[0][t>>5]=s; sh[1][t>>5]=s2; }
    __syncthreads();
    if (t < 32){
        s  = (t<8)? sh[0][t] : 0.f;
        s2 = (t<8)? sh[1][t] : 0.f;
#pragma unroll
        for (int o=4;o;o>>=1){ s += __shfl_xor_sync(0xffffffffu,s,o); s2 += __shfl_xor_sync(0xffffffffu,s2,o); }
        if (t==0){ sh[0][0]=s; sh[1][0]=s2; }
    }
    __syncthreads();
    float mu  = sh[0][0]*(1.f/EMB);
    float var = sh[1][0]*(1.f/EMB) - mu*mu;
    float inv = rsqrtf(var + 1e-5f);
    __nv_bfloat16* q = out + (size_t)row*QKV3;
#pragma unroll
    for (int i=0;i<3;i++){
        int e = t + i*256;
        float nv = (v[i]-mu)*inv;
        __nv_bfloat16 hi = __float2bfloat16(nv);
        __nv_bfloat16 lo = __float2bfloat16(nv - __bfloat162float(hi));
        q[e] = hi;
        q[EMB + e] = lo;
        q[2*EMB + e] = hi;
    }
}

__global__ void lnfinal_k(const float* __restrict__ X, const float* __restrict__ g,
                          const float* __restrict__ bta, float* __restrict__ out)
{
    int b = blockIdx.x;
    const float* p = X + (size_t)b*SEQ*EMB;
    int t = threadIdx.x;
    float v[3]; float s=0.f, s2=0.f;
#pragma unroll
    for (int i=0;i<3;i++){ v[i]=p[t + i*256]; s+=v[i]; s2+=v[i]*v[i]; }
    __shared__ float sh[2][8];
#pragma unroll
    for (int o=16;o;o>>=1){ s += __shfl_xor_sync(0xffffffffu,s,o); s2 += __shfl_xor_sync(0xffffffffu,s2,o); }
    if ((t&31)==0){ sh[0][t>>5]=s; sh[1][t>>5]=s2; }
    __syncthreads();
    if (t < 32){
        s  = (t<8)? sh[0][t] : 0.f;
        s2 = (t<8)? sh[1][t] : 0.f;
#pragma unroll
        for (int o=4;o;o>>=1){ s += __shfl_xor_sync(0xffffffffu,s,o); s2 += __shfl_xor_sync(0xffffffffu,s2,o); }
        if (t==0){ sh[0][0]=s; sh[1][0]=s2; }
    }
    __syncthreads();
    float mu  = sh[0][0]*(1.f/EMB);
    float var = sh[1][0]*(1.f/EMB) - mu*mu;
    float inv = rsqrtf(var + 1e-5f);
#pragma unroll
    for (int i=0;i<3;i++){
        int e = t + i*256;
        out[(size_t)b*EMB + e] = (v[i]-mu)*inv*g[e] + bta[e];
    }
}

__global__ void head_k(const float* __restrict__ cls, const float* __restrict__ hw,
                       const float* __restrict__ hb, float* __restrict__ out)
{
    int t = threadIdx.x;
    if (t >= BATCH*10) return;
    int b = t/10, c = t - b*10;
    float s = __ldg(hb + c);
    const float* crow = cls + (size_t)b*EMB;
    for (int e=0;e<EMB;e++) s += crow[e]*__ldg(hw + (size_t)e*10 + c);
    out[t] = s;
}

// ---------------- launch ----------------------------------------------------
extern "C" void kernel_launch(void* const* d_in, const int* in_sizes, int n_in,
                              void* d_out, int out_size)
{
    (void)in_sizes; (void)n_in; (void)out_size;
    const float* img     = (const float*)d_in[0];
    const float* patch_w = (const float*)d_in[1];
    const float* patch_b = (const float*)d_in[2];
    const float* cls_tok = (const float*)d_in[3];
    const float* pos_emb = (const float*)d_in[4];
    const float* qkv_w   = (const float*)d_in[5];
    const float* fc_w    = (const float*)d_in[6];
    const float* mlp_w1  = (const float*)d_in[7];
    const float* mlp_b1  = (const float*)d_in[8];
    const float* mlp_w2  = (const float*)d_in[9];
    const float* mlp_b2  = (const float*)d_in[10];
    const float* ln_g    = (const float*)d_in[11];
    const float* ln_b    = (const float*)d_in[12];
    const float* head_w  = (const float*)d_in[13];
    const float* head_b  = (const float*)d_in[14];
    float* out = (float*)d_out;

    static float *x=nullptr,*qkv=nullptr,*clsb=nullptr;
    static __nv_bfloat16 *hx3=nullptr,*ox3=nullptr,*mx3=nullptr,*wq=nullptr,*wf=nullptr,*w1=nullptr,*w2=nullptr;
    if (!x){
        cudaGetSymbolAddress((void**)&x,    g_x);
        cudaGetSymbolAddress((void**)&qkv,  g_qkv);
        cudaGetSymbolAddress((void**)&clsb, g_cls);
        cudaGetSymbolAddress((void**)&hx3,  g_hx3);
        cudaGetSymbolAddress((void**)&ox3,  g_ox3);
        cudaGetSymbolAddress((void**)&mx3,  g_mx3);
        cudaGetSymbolAddress((void**)&wq,   g_wq);
        cudaGetSymbolAddress((void**)&wf,   g_wf);
        cudaGetSymbolAddress((void**)&w1,   g_w1);
        cudaGetSymbolAddress((void**)&w2,   g_w2);
        cudaFuncSetAttribute(tgemm, cudaFuncAttributeMaxDynamicSharedMemorySize, SM_TOTAL);
        cudaFuncSetAttribute(fattn, cudaFuncAttributeMaxDynamicSharedMemorySize, FA_SMEM);
    }

    // weight split+transpose (bf16 x3), all layers
    wconv<<<dim3(EMB/32,  QKV3/32, NLAYER), dim3(32,8)>>>(qkv_w,  wq, EMB,  QKV3);
    wconv<<<dim3(EMB/32,  EMB/32,  NLAYER), dim3(32,8)>>>(fc_w,   wf, EMB,  EMB);
    wconv<<<dim3(EMB/32,  MLPD/32, NLAYER), dim3(32,8)>>>(mlp_w1, w1, EMB,  MLPD);
    wconv<<<dim3(MLPD/32, EMB/32,  NLAYER), dim3(32,8)>>>(mlp_w2, w2, MLPD, EMB);

    patch_gemm<<<dim3(6,49),256>>>(img, patch_w, patch_b, pos_emb, x);
    cls_init<<<(BATCH*EMB+255)/256,256>>>(cls_tok, pos_emb, x);

    for (int l=0; l<NLAYER; l++){
        ln_x3<<<ROWS,256>>>(x, hx3);
        tgemm<<<dim3(QKV3/128, ROWS_PAD/128), 256, SM_TOTAL>>>(
            hx3, wq + (size_t)l*QKV3*QKV3, QKV3, 36, qkv, QKV3, nullptr, nullptr, 0);
        fattn<<<dim3(7, BHEADS), 256, FA_SMEM>>>(qkv, ox3);
        tgemm<<<dim3(EMB/128, ROWS_PAD/128), 256, SM_TOTAL>>>(
            ox3, wf + (size_t)l*EMB*QKV3, QKV3, 36, x, EMB, nullptr, nullptr, 1);
        ln_x3<<<ROWS,256>>>(x, hx3);
        tgemm<<<dim3(MLPD/128, ROWS_PAD/128), 256, SM_TOTAL>>>(
            hx3, w1 + (size_t)l*MLPD*QKV3, QKV3, 36, nullptr, 0,
            mlp_b1 + (size_t)l*MLPD, mx3, 2);
        tgemm<<<dim3(EMB/128, ROWS_PAD/128), 256, SM_TOTAL>>>(
            mx3, w2 + (size_t)l*EMB*3*MLPD, 3*MLPD, 144, x, EMB,
            mlp_b2 + (size_t)l*EMB, nullptr, 3);
    }

    lnfinal_k<<<BATCH,256>>>(x, ln_g, ln_b, clsb);
    head_k<<<1,512>>>(clsb, head_w, head_b, out);
}

// round 10
// speedup vs baseline: 2.4947x; 1.2114x over previous
#include <cuda_runtime.h>
#include <cuda_bf16.h>
#include <math.h>
#include <stdint.h>

#define BATCH 32
#define SEQ 197
#define EMB 768
#define NHEAD 12
#define HDIM 64
#define QKV3 2304
#define MLPD 3072
#define NLAYER 12
#define ROWS (BATCH*SEQ)      /* 6304 */
#define ROWS_PAD 6400         /* 50*128 */
#define BHEADS (BATCH*NHEAD)  /* 384 */
#define NPATCH 196

// ---------------- scratch (static device globals) ---------------------------
__device__ float g_x[ROWS_PAD*EMB];
__device__ float g_qkv[ROWS_PAD*QKV3];
__device__ float g_cls[BATCH*EMB];
__device__ __nv_bfloat16 g_hx3[(size_t)ROWS_PAD*QKV3];   // LN out, x3 split (K'=2304)
__device__ __nv_bfloat16 g_ox3[(size_t)ROWS_PAD*QKV3];   // attn out, x3 split
__device__ __nv_bfloat16 g_mx3[(size_t)ROWS_PAD*3*MLPD]; // mlp mid, x3 split (K'=9216)
__device__ __nv_bfloat16 g_wq[(size_t)NLAYER*QKV3*QKV3];  // qkv_w^T x3
__device__ __nv_bfloat16 g_wf[(size_t)NLAYER*EMB*QKV3];   // fc_w^T  x3
__device__ __nv_bfloat16 g_w1[(size_t)NLAYER*MLPD*QKV3];  // w1^T    x3
__device__ __nv_bfloat16 g_w2[(size_t)NLAYER*EMB*3*MLPD]; // w2^T    x3

__device__ __forceinline__ float gelu_f(float x){
    float x3 = x*x*x;
    return 0.5f*x*(1.0f + tanhf(0.7978845608028654f*(x + 0.044715f*x3)));
}

__device__ __forceinline__ uint32_t smem_u32(const void* p){
    uint32_t a;
    asm("{ .reg .u64 t; cvta.to.shared.u64 t, %1; cvt.u32.u64 %0, t; }" : "=r"(a) : "l"(p));
    return a;
}

#define LDSM4(r0,r1,r2,r3, addr) \
    asm volatile("ldmatrix.sync.aligned.m8n8.x4.shared.b16 {%0,%1,%2,%3}, [%4];" \
        : "=r"(r0),"=r"(r1),"=r"(r2),"=r"(r3) : "r"(addr))

#define MMA16816(d, a0,a1,a2,a3, b0,b1) \
    asm volatile("mma.sync.aligned.m16n8k16.row.col.f32.bf16.bf16.f32 " \
        "{%0,%1,%2,%3}, {%4,%5,%6,%7}, {%8,%9}, {%0,%1,%2,%3};" \
        : "+f"((d)[0]),"+f"((d)[1]),"+f"((d)[2]),"+f"((d)[3]) \
        : "r"(a0),"r"(a1),"r"(a2),"r"(a3), "r"(b0),"r"(b1))

#define CPA16(dst, src) \
    asm volatile("cp.async.cg.shared.global [%0], [%1], 16;" :: "r"(dst), "l"(src) : "memory")
#define CPA_COMMIT() asm volatile("cp.async.commit_group;" ::: "memory")
#define CPA_WAIT0()  asm volatile("cp.async.wait_group 0;" ::: "memory")

// ---------------- tensor-core GEMM (mma.sync bf16, cp.async pipeline) -------
#define SA0 0
#define SB0 16384
#define SA1 32768
#define SB1 49152
#define SM_TOTAL 65536

__global__ void __launch_bounds__(256,2) tgemm(
    const __nv_bfloat16* __restrict__ A, const __nv_bfloat16* __restrict__ Bt,
    int ldk, int NC,
    float* __restrict__ outf, int ldo, const float* __restrict__ bias,
    __nv_bfloat16* __restrict__ outx3, int epi)
{
    extern __shared__ char dsm[];
    const int tid = threadIdx.x;
    const int wid = tid >> 5;
    const int lane = tid & 31;
    const int warp_m = wid & 1;
    const int warp_n = wid >> 1;
    const int rowBase = blockIdx.y * 128;
    const int colBase = blockIdx.x * 128;
    const uint32_t sbase = smem_u32(dsm);

    const __nv_bfloat16* Ab = A  + (size_t)rowBase * ldk;
    const __nv_bfloat16* Bb = Bt + (size_t)colBase * ldk;

    float acc[4][4][4];
#pragma unroll
    for (int mt=0;mt<4;mt++)
#pragma unroll
      for (int nt=0;nt<4;nt++)
#pragma unroll
        for (int j=0;j<4;j++) acc[mt][nt][j]=0.f;

    const int lA_row = warp_m*64 + (lane & 15);
    const int lA_kb  = (lane >> 4) * 16;
    const int g      = lane >> 3;
    const int lB_row = warp_n*32 + (lane & 7) + (g >> 1) * 8;
    const int lB_kb  = (g & 1) * 16;

    // loader: thread tid handles rows/cols (r = idx>>3, c = idx&7), 16B each
    const int ldr_r = tid >> 3;          // base row (0..31), +32 per i
    const int ldr_c = tid & 7;           // 16B column within 128B row

    const uint32_t saoff[2] = {SA0, SA1};
    const uint32_t sboff[2] = {SB0, SB1};

    // preload chunk 0 into buf 0 via cp.async
#pragma unroll
    for (int i=0;i<4;i++){
        int r = ldr_r + i*32;
        uint32_t off = r*128 + ldr_c*16;
        off ^= (off>>3)&0x70;
        CPA16(sbase + SA0 + off, Ab + (size_t)r*ldk + ldr_c*8);
        CPA16(sbase + SB0 + off, Bb + (size_t)r*ldk + ldr_c*8);
    }
    CPA_COMMIT();

    for (int c = 0; c < NC; c++){
        int cur = c & 1;
        CPA_WAIT0();
        __syncthreads();   // current buffer ready AND prior reads of other buffer done

        if (c + 1 < NC){
            int nb = cur ^ 1;
            int k0 = (c+1)*64;
#pragma unroll
            for (int i=0;i<4;i++){
                int r = ldr_r + i*32;
                uint32_t off = r*128 + ldr_c*16;
                off ^= (off>>3)&0x70;
                CPA16(sbase + saoff[nb] + off, Ab + (size_t)r*ldk + k0 + ldr_c*8);
                CPA16(sbase + sboff[nb] + off, Bb + (size_t)r*ldk + k0 + ldr_c*8);
            }
            CPA_COMMIT();
        }

        uint32_t sa = sbase + saoff[cur];
        uint32_t sb = sbase + sboff[cur];
#pragma unroll
        for (int ks=0; ks<4; ks++){
            uint32_t af[4][4], bf[2][4];
#pragma unroll
            for (int mt=0;mt<4;mt++){
                int row = lA_row + mt*16;
                uint32_t off = row*128 + ks*32 + lA_kb;
                off ^= (off>>3)&0x70;
                LDSM4(af[mt][0],af[mt][1],af[mt][2],af[mt][3], sa + off);
            }
#pragma unroll
            for (int bt=0;bt<2;bt++){
                int row = lB_row + bt*16;
                uint32_t off = row*128 + ks*32 + lB_kb;
                off ^= (off>>3)&0x70;
                LDSM4(bf[bt][0],bf[bt][1],bf[bt][2],bf[bt][3], sb + off);
            }
#pragma unroll
            for (int mt=0;mt<4;mt++)
#pragma unroll
              for (int nt=0;nt<4;nt++){
                  uint32_t b0 = bf[nt>>1][(nt&1)*2];
                  uint32_t b1 = bf[nt>>1][(nt&1)*2+1];
                  MMA16816(acc[mt][nt], af[mt][0],af[mt][1],af[mt][2],af[mt][3], b0,b1);
              }
        }
    }
    __syncthreads();

    const int grp = lane >> 2;
    const int thc = (lane & 3) * 2;
#pragma unroll
    for (int mt=0;mt<4;mt++){
#pragma unroll
        for (int half=0; half<2; half++){
            int grow = rowBase + warp_m*64 + mt*16 + grp + half*8;
            if (grow >= ROWS) continue;
#pragma unroll
            for (int nt=0;nt<4;nt++){
                float v0 = acc[mt][nt][half*2+0];
                float v1 = acc[mt][nt][half*2+1];
                int gcol = colBase + warp_n*32 + nt*8 + thc;
                if (epi == 0){
                    float2* p = (float2*)(outf + (size_t)grow*ldo + gcol);
                    *p = make_float2(v0, v1);
                } else if (epi == 1){
                    float2* p = (float2*)(outf + (size_t)grow*EMB + gcol);
                    float2 x = *p;
                    x.x += v0; x.y += v1;
                    *p = x;
                } else if (epi == 2){
                    float t0 = gelu_f(v0 + bias[gcol]);
                    float t1 = gelu_f(v1 + bias[gcol+1]);
                    __nv_bfloat16 h0 = __float2bfloat16(t0);
                    __nv_bfloat16 l0 = __float2bfloat16(t0 - __bfloat162float(h0));
                    __nv_bfloat16 h1 = __float2bfloat16(t1);
                    __nv_bfloat16 l1 = __float2bfloat16(t1 - __bfloat162float(h1));
                    __nv_bfloat16* prow = outx3 + (size_t)grow*3*MLPD;
                    *(__nv_bfloat162*)(prow + gcol)            = __nv_bfloat162(h0,h1);
                    *(__nv_bfloat162*)(prow + MLPD + gcol)     = __nv_bfloat162(l0,l1);
                    *(__nv_bfloat162*)(prow + 2*MLPD + gcol)   = __nv_bfloat162(h0,h1);
                } else {
                    float2* p = (float2*)(outf + (size_t)grow*EMB + gcol);
                    float2 x = *p;
                    x.x += v0 + bias[gcol]; x.y += v1 + bias[gcol+1];
                    *p = x;
                }
            }
        }
    }
}

// ---------------- fused attention, conservative SMEM (59.7 KB) --------------
#define FA_KS 0          /* K region: 197*65 = 12805 floats; later Ps (needs 6400) */
#define FA_QS 12806      /* EVEN base: Q (32*65=2080); later V chunk (32*66=2112) */
#define FA_FLOATS (FA_QS + 2112)   /* 14918 */
#define FA_SMEM (FA_FLOATS*4)      /* 59672 B */

__global__ void __launch_bounds__(256) fattn(const float* __restrict__ qkv,
                                             __nv_bfloat16* __restrict__ ox3)
{
    extern __shared__ float fsm[];
    float* Ks = fsm + FA_KS;
    float* Qs = fsm + FA_QS;
    float* Ps = fsm + FA_KS;   // alias: valid after post-scores barrier (scalar access)
    float* Vs = fsm + FA_QS;   // alias: even base, stride 66 -> float2-aligned
    const int tid = threadIdx.x, wid = tid >> 5, lane = tid & 31;
    const int bh = blockIdx.y;
    const int b = bh / NHEAD, h = bh - b*NHEAD;
    const int q0 = blockIdx.x * 32;
    const float* base = qkv + (size_t)b*SEQ*QKV3 + h*HDIM;

    for (int idx = tid; idx < SEQ*16; idx += 256){
        int r = idx >> 4, c4 = (idx & 15) << 2;
        float4 v = *(const float4*)(base + EMB + (size_t)r*QKV3 + c4);
        float* d = Ks + r*65 + c4;
        d[0]=v.x; d[1]=v.y; d[2]=v.z; d[3]=v.w;
    }
    for (int idx = tid; idx < 32*16; idx += 256){
        int r = idx >> 4, c4 = (idx & 15) << 2;
        int qr = q0 + r;
        float4 v = make_float4(0.f,0.f,0.f,0.f);
        if (qr < SEQ) v = *(const float4*)(base + (size_t)qr*QKV3 + c4);
        float* d = Qs + r*65 + c4;
        d[0]=v.x; d[1]=v.y; d[2]=v.z; d[3]=v.w;
    }
    __syncthreads();

    float s[4][7];
#pragma unroll
    for (int r=0;r<4;r++)
#pragma unroll
      for (int kk=0;kk<7;kk++) s[r][kk]=0.f;

    for (int d0=0; d0<HDIM; d0+=4){
        float q[4][4], k[7][4];
#pragma unroll
        for (int r=0;r<4;r++){
            const float* qp = Qs + (wid*4+r)*65 + d0;
            q[r][0]=qp[0]; q[r][1]=qp[1]; q[r][2]=qp[2]; q[r][3]=qp[3];
        }
#pragma unroll
        for (int kk=0;kk<7;kk++){
            const float* kp = Ks + (lane+32*kk)*65 + d0;
            k[kk][0]=kp[0]; k[kk][1]=kp[1]; k[kk][2]=kp[2]; k[kk][3]=kp[3];
        }
#pragma unroll
        for (int r=0;r<4;r++)
#pragma unroll
          for (int kk=0;kk<7;kk++)
#pragma unroll
            for (int j=0;j<4;j++)
                s[r][kk] += q[r][j]*k[kk][j];
    }

    float invs[4];
#pragma unroll
    for (int r=0;r<4;r++){
        float mx = -1e30f;
#pragma unroll
        for (int kk=0;kk<7;kk++){
            int key = lane + 32*kk;
            s[r][kk] = (key < SEQ) ? s[r][kk]*0.125f : -1e30f;
            mx = fmaxf(mx, s[r][kk]);
        }
#pragma unroll
        for (int o=16;o;o>>=1) mx = fmaxf(mx, __shfl_xor_sync(0xffffffffu, mx, o));
        float sum = 0.f;
#pragma unroll
        for (int kk=0;kk<7;kk++){
            float p = __expf(s[r][kk]-mx);
            s[r][kk] = p; sum += p;
        }
#pragma unroll
        for (int o=16;o;o>>=1) sum += __shfl_xor_sync(0xffffffffu, sum, o);
        invs[r] = 1.f/sum;
    }

    __syncthreads();   // retire all Ks/Qs reads before aliasing

#pragma unroll
    for (int r=0;r<4;r++){
#pragma unroll
        for (int kk=0;kk<7;kk++){
            int key = lane + 32*kk;
            if (key < SEQ) Ps[(wid*4+r)*200 + key] = s[r][kk];
        }
    }

    float o[4][2];
#pragma unroll
    for (int r=0;r<4;r++){ o[r][0]=0.f; o[r][1]=0.f; }

    for (int kt=0; kt<SEQ; kt+=32){
        int nrows = SEQ - kt; if (nrows > 32) nrows = 32;
        __syncthreads();
        for (int idx = tid; idx < nrows*16; idx += 256){
            int r = idx >> 4, c4 = (idx & 15) << 2;
            float4 v = *(const float4*)(base + 2*EMB + (size_t)(kt+r)*QKV3 + c4);
            float* d = Vs + r*66 + c4;
            d[0]=v.x; d[1]=v.y; d[2]=v.z; d[3]=v.w;
        }
        __syncthreads();
        for (int kl=0; kl<nrows; kl++){
            float2 vv = *(float2*)(Vs + kl*66 + lane*2);
#pragma unroll
            for (int r=0;r<4;r++){
                float p = Ps[(wid*4+r)*200 + kt + kl];
                o[r][0] += p*vv.x; o[r][1] += p*vv.y;
            }
        }
    }

#pragma unroll
    for (int r=0;r<4;r++){
        int qr = q0 + wid*4 + r;
        if (qr >= SEQ) continue;
        float v0 = o[r][0]*invs[r], v1 = o[r][1]*invs[r];
        __nv_bfloat16 h0=__float2bfloat16(v0), l0=__float2bfloat16(v0-__bfloat162float(h0));
        __nv_bfloat16 h1=__float2bfloat16(v1), l1=__float2bfloat16(v1-__bfloat162float(h1));
        __nv_bfloat16* orow = ox3 + ((size_t)b*SEQ + qr)*QKV3;
        int col = h*HDIM + lane*2;
        *(__nv_bfloat162*)(orow + col)         = __nv_bfloat162(h0,h1);
        *(__nv_bfloat162*)(orow + EMB + col)   = __nv_bfloat162(l0,l1);
        *(__nv_bfloat162*)(orow + 2*EMB + col) = __nv_bfloat162(h0,h1);
    }
}

// ---------------- weight convert: (L,K,N) fp32 -> (L,N,3K) bf16 [hi|hi|lo] --
__global__ void wconv(const float* __restrict__ src, __nv_bfloat16* __restrict__ dst,
                      int K, int N)
{
    int l = blockIdx.z;
    src += (size_t)l*K*N;
    dst += (size_t)l*N*3*K;
    __shared__ float sm[32][33];
    int k0 = blockIdx.x*32, n0 = blockIdx.y*32;
#pragma unroll
    for (int i=0;i<4;i++){
        int k = k0 + threadIdx.y + i*8;
        sm[threadIdx.y + i*8][threadIdx.x] = src[(size_t)k*N + n0 + threadIdx.x];
    }
    __syncthreads();
#pragma unroll
    for (int i=0;i<4;i++){
        int n = n0 + threadIdx.y + i*8;
        int k = k0 + threadIdx.x;
        float v = sm[threadIdx.x][threadIdx.y + i*8];
        __nv_bfloat16 hi = __float2bfloat16(v);
        __nv_bfloat16 lo = __float2bfloat16(v - __bfloat162float(hi));
        __nv_bfloat16* drow = dst + (size_t)n*3*K;
        drow[k] = hi;
        drow[K + k] = hi;
        drow[2*K + k] = lo;
    }
}

// ---------------- patch-embed GEMM (fp32) -----------------------------------
__global__ __launch_bounds__(256,2) void patch_gemm(
    const float* __restrict__ img, const float* __restrict__ Bw,
    const float* __restrict__ pbias, const float* __restrict__ pos,
    float* __restrict__ X)
{
    __shared__ float As[16][132];
    __shared__ float Bs[16][132];
    const int tid = threadIdx.x;
    const int rowBase = blockIdx.y * 128;
    const int colBase = blockIdx.x * 128;
    const int ty = tid >> 4, tx = tid & 15;

    float acc[2][2][4][4];
#pragma unroll
    for (int a=0;a<2;a++)
#pragma unroll
      for (int b=0;b<2;b++)
#pragma unroll
        for (int i=0;i<4;i++)
#pragma unroll
          for (int j=0;j<4;j++) acc[a][b][i][j]=0.f;

    for (int k0 = 0; k0 < EMB; k0 += 16) {
#pragma unroll
        for (int i=0;i<2;i++){
            int idx = tid + i*256;
            int r = idx >> 2;
            int c4 = (idx & 3) << 2;
            int gr = rowBase + r;
            int gk = k0 + c4;
            int b  = gr / NPATCH;
            int n  = gr - b*NPATCH;
            int pr = n / 14, pc = n - pr*14;
            int ch = gk >> 8;
            int py = (gk >> 4) & 15;
            int px = gk & 15;
            const float* src = img + ((((size_t)(b*3+ch))*224 + pr*16+py)*224 + pc*16 + px);
            float4 v = *(const float4*)src;
            As[c4+0][r]=v.x; As[c4+1][r]=v.y; As[c4+2][r]=v.z; As[c4+3][r]=v.w;
        }
#pragma unroll
        for (int i=0;i<2;i++){
            int idx = tid + i*256;
            int r = idx >> 5;
            int c4 = (idx & 31) << 2;
            *(float4*)&Bs[r][c4] = *(const float4*)(Bw + (size_t)(k0+r)*EMB + colBase + c4);
        }
        __syncthreads();
#pragma unroll
        for (int k=0;k<16;k++){
            float av[2][4], bv[2][4];
            *(float4*)&av[0][0] = *(const float4*)&As[k][ty*4];
            *(float4*)&av[1][0] = *(const float4*)&As[k][ty*4 + 64];
            *(float4*)&bv[0][0] = *(const float4*)&Bs[k][tx*4];
            *(float4*)&bv[1][0] = *(const float4*)&Bs[k][tx*4 + 64];
#pragma unroll
            for (int a=0;a<2;a++)
#pragma unroll
              for (int i=0;i<4;i++)
#pragma unroll
                for (int b=0;b<2;b++)
#pragma unroll
                  for (int j=0;j<4;j++)
                    acc[a][b][i][j] += av[a][i]*bv[b][j];
        }
        __syncthreads();
    }

#pragma unroll
    for (int a=0;a<2;a++){
#pragma unroll
        for (int b=0;b<2;b++){
            int r0 = rowBase + ty*4 + a*64;
            int c0 = colBase + tx*4 + b*64;
#pragma unroll
            for (int i=0;i<4;i++){
                int r = r0 + i;
                int bb = r / NPATCH;
                int n  = r - bb*NPATCH;
                float* Xrow = X + ((size_t)(bb*SEQ) + 1 + n)*EMB + c0;
                const float* prow = pos + (size_t)(1+n)*EMB + c0;
#pragma unroll
                for (int j=0;j<4;j++)
                    Xrow[j] = acc[a][b][i][j] + pbias[c0+j] + prow[j];
            }
        }
    }
}

__global__ void cls_init(const float* __restrict__ cls, const float* __restrict__ pos,
                         float* __restrict__ X)
{
    int idx = blockIdx.x*256 + threadIdx.x;
    if (idx >= BATCH*EMB) return;
    int b = idx / EMB, e = idx - b*EMB;
    X[(size_t)b*SEQ*EMB + e] = cls[e] + pos[e];
}

// ---------------- layernorm -> bf16 x3 [hi|lo|hi] ---------------------------
__global__ void ln_x3(const float* __restrict__ in, __nv_bfloat16* __restrict__ out)
{
    int row = blockIdx.x;
    const float* p = in + (size_t)row*EMB;
    int t = threadIdx.x;
    float v[3]; float s=0.f, s2=0.f;
#pragma unroll
    for (int i=0;i<3;i++){ v[i]=p[t + i*256]; s+=v[i]; s2+=v[i]*v[i]; }
    __shared__ float sh[2][8];
#pragma unroll
    for (int o=16;o;o>>=1){ s += __shfl_xor_sync(0xffffffffu,s,o); s2 += __shfl_xor_sync(0xffffffffu,s2,o); }
    if ((t&31)==0){ sh[0][t>>5]=s; sh[1][t>>5]=s2; }
    __syncthreads();
    if (t < 32){
        s  = (t<8)? sh[0][t] : 0.f;
        s2 = (t<8)? sh[1][t] : 0.f;
#pragma unroll
        for (int o=4;o;o>>=1){ s += __shfl_xor_sync(0xffffffffu,s,o); s2 += __shfl_xor_sync(0xffffffffu,s2,o); }
        if (t==0){ sh[0][0]=s; sh[1][0]=s2; }
    }
    __syncthreads();
    float mu  = sh[0][0]*(1.f/EMB);
    float var = sh[1][0]*(1.f/EMB) - mu*mu;
    float inv = rsqrtf(var + 1e-5f);
    __nv_bfloat16* q = out + (size_t)row*QKV3;
#pragma unroll
    for (int i=0;i<3;i++){
        int e = t + i*256;
        float nv = (v[i]-mu)*inv;
        __nv_bfloat16 hi = __float2bfloat16(nv);
        __nv_bfloat16 lo = __float2bfloat16(nv - __bfloat162float(hi));
        q[e] = hi;
        q[EMB + e] = lo;
        q[2*EMB + e] = hi;
    }
}

__global__ void lnfinal_k(const float* __restrict__ X, const float* __restrict__ g,
                          const float* __restrict__ bta, float* __restrict__ out)
{
    int b = blockIdx.x;
    const float* p = X + (size_t)b*SEQ*EMB;
    int t = threadIdx.x;
    float v[3]; float s=0.f, s2=0.f;
#pragma unroll
    for (int i=0;i<3;i++){ v[i]=p[t + i*256]; s+=v[i]; s2+=v[i]*v[i]; }
    __shared__ float sh[2][8];
#pragma unroll
    for (int o=16;o;o>>=1){ s += __shfl_xor_sync(0xffffffffu,s,o); s2 += __shfl_xor_sync(0xffffffffu,s2,o); }
    if ((t&31)==0){ sh[0][t>>5]=s; sh[1][t>>5]=s2; }
    __syncthreads();
    if (t < 32){
        s  = (t<8)? sh[0][t] : 0.f;
        s2 = (t<8)? sh[1][t] : 0.f;
#pragma unroll
        for (int o=4;o;o>>=1){ s += __shfl_xor_sync(0xffffffffu,s,o); s2 += __shfl_xor_sync(0xffffffffu,s2,o); }
        if (t==0){ sh[0][0]=s; sh[1][0]=s2; }
    }
    __syncthreads();
    float mu  = sh[0][0]*(1.f/EMB);
    float var = sh[1][0]*(1.f/EMB) - mu*mu;
    float inv = rsqrtf(var + 1e-5f);
#pragma unroll
    for (int i=0;i<3;i++){
        int e = t + i*256;
        out[(size_t)b*EMB + e] = (v[i]-mu)*inv*g[e] + bta[e];
    }
}

__global__ void head_k(const float* __restrict__ cls, const float* __restrict__ hw,
                       const float* __restrict__ hb, float* __restrict__ out)
{
    int t = threadIdx.x;
    if (t >= BATCH*10) return;
    int b = t/10, c = t - b*10;
    float s = __ldg(hb + c);
    const float* crow = cls + (size_t)b*EMB;
    for (int e=0;e<EMB;e++) s += crow[e]*__ldg(hw + (size_t)e*10 + c);
    out[t] = s;
}

// ---------------- launch ----------------------------------------------------
extern "C" void kernel_launch(void* const* d_in, const int* in_sizes, int n_in,
                              void* d_out, int out_size)
{
    (void)in_sizes; (void)n_in; (void)out_size;
    const float* img     = (const float*)d_in[0];
    const float* patch_w = (const float*)d_in[1];
    const float* patch_b = (const float*)d_in[2];
    const float* cls_tok = (const float*)d_in[3];
    const float* pos_emb = (const float*)d_in[4];
    const float* qkv_w   = (const float*)d_in[5];
    const float* fc_w    = (const float*)d_in[6];
    const float* mlp_w1  = (const float*)d_in[7];
    const float* mlp_b1  = (const float*)d_in[8];
    const float* mlp_w2  = (const float*)d_in[9];
    const float* mlp_b2  = (const float*)d_in[10];
    const float* ln_g    = (const float*)d_in[11];
    const float* ln_b    = (const float*)d_in[12];
    const float* head_w  = (const float*)d_in[13];
    const float* head_b  = (const float*)d_in[14];
    float* out = (float*)d_out;

    static float *x=nullptr,*qkv=nullptr,*clsb=nullptr;
    static __nv_bfloat16 *hx3=nullptr,*ox3=nullptr,*mx3=nullptr,*wq=nullptr,*wf=nullptr,*w1=nullptr,*w2=nullptr;
    if (!x){
        cudaGetSymbolAddress((void**)&x,    g_x);
        cudaGetSymbolAddress((void**)&qkv,  g_qkv);
        cudaGetSymbolAddress((void**)&clsb, g_cls);
        cudaGetSymbolAddress((void**)&hx3,  g_hx3);
        cudaGetSymbolAddress((void**)&ox3,  g_ox3);
        cudaGetSymbolAddress((void**)&mx3,  g_mx3);
        cudaGetSymbolAddress((void**)&wq,   g_wq);
        cudaGetSymbolAddress((void**)&wf,   g_wf);
        cudaGetSymbolAddress((void**)&w1,   g_w1);
        cudaGetSymbolAddress((void**)&w2,   g_w2);
        cudaFuncSetAttribute(tgemm, cudaFuncAttributeMaxDynamicSharedMemorySize, SM_TOTAL);
        cudaFuncSetAttribute(fattn, cudaFuncAttributeMaxDynamicSharedMemorySize, FA_SMEM);
    }

    // weight split+transpose (bf16 x3), all layers
    wconv<<<dim3(EMB/32,  QKV3/32, NLAYER), dim3(32,8)>>>(qkv_w,  wq, EMB,  QKV3);
    wconv<<<dim3(EMB/32,  EMB/32,  NLAYER), dim3(32,8)>>>(fc_w,   wf, EMB,  EMB);
    wconv<<<dim3(EMB/32,  MLPD/32, NLAYER), dim3(32,8)>>>(mlp_w1, w1, EMB,  MLPD);
    wconv<<<dim3(MLPD/32, EMB/32,  NLAYER), dim3(32,8)>>>(mlp_w2, w2, MLPD, EMB);

    patch_gemm<<<dim3(6,49),256>>>(img, patch_w, patch_b, pos_emb, x);
    cls_init<<<(BATCH*EMB+255)/256,256>>>(cls_tok, pos_emb, x);

    for (int l=0; l<NLAYER; l++){
        ln_x3<<<ROWS,256>>>(x, hx3);
        tgemm<<<dim3(QKV3/128, ROWS_PAD/128), 256, SM_TOTAL>>>(
            hx3, wq + (size_t)l*QKV3*QKV3, QKV3, 36, qkv, QKV3, nullptr, nullptr, 0);
        fattn<<<dim3(7, BHEADS), 256, FA_SMEM>>>(qkv, ox3);
        tgemm<<<dim3(EMB/128, ROWS_PAD/128), 256, SM_TOTAL>>>(
            ox3, wf + (size_t)l*EMB*QKV3, QKV3, 36, x, EMB, nullptr, nullptr, 1);
        ln_x3<<<ROWS,256>>>(x, hx3);
        tgemm<<<dim3(MLPD/128, ROWS_PAD/128), 256, SM_TOTAL>>>(
            hx3, w1 + (size_t)l*MLPD*QKV3, QKV3, 36, nullptr, 0,
            mlp_b1 + (size_t)l*MLPD, mx3, 2);
        tgemm<<<dim3(EMB/128, ROWS_PAD/128), 256, SM_TOTAL>>>(
            mx3, w2 + (size_t)l*EMB*3*MLPD, 3*MLPD, 144, x, EMB,
            mlp_b2 + (size_t)l*EMB, nullptr, 3);
    }

    lnfinal_k<<<BATCH,256>>>(x, ln_g, ln_b, clsb);
    head_k<<<1,512>>>(clsb, head_w, head_b, out);
}

// round 13
// speedup vs baseline: 2.6116x; 1.0469x over previous
#include <cuda_runtime.h>
#include <cuda_bf16.h>
#include <math.h>
#include <stdint.h>

#define BATCH 32
#define SEQ 197
#define EMB 768
#define NHEAD 12
#define HDIM 64
#define QKV3 2304
#define MLPD 3072
#define NLAYER 12
#define ROWS (BATCH*SEQ)      /* 6304 */
#define ROWS_PAD 6400         /* 50*128 */
#define BHEADS (BATCH*NHEAD)  /* 384 */
#define NPATCH 196

// ---------------- scratch (static device globals) ---------------------------
__device__ float g_x[ROWS_PAD*EMB];
__device__ float g_qkv[ROWS_PAD*QKV3];
__device__ float g_cls[BATCH*EMB];
__device__ __nv_bfloat16 g_hx3[(size_t)ROWS_PAD*QKV3];   // LN out, x3 split (K'=2304)
__device__ __nv_bfloat16 g_ox3[(size_t)ROWS_PAD*QKV3];   // attn out, x3 split
__device__ __nv_bfloat16 g_mx3[(size_t)ROWS_PAD*3*MLPD]; // mlp mid, x3 split (K'=9216)
__device__ __nv_bfloat16 g_wq[(size_t)NLAYER*QKV3*QKV3];  // qkv_w^T x3
__device__ __nv_bfloat16 g_wf[(size_t)NLAYER*EMB*QKV3];   // fc_w^T  x3
__device__ __nv_bfloat16 g_w1[(size_t)NLAYER*MLPD*QKV3];  // w1^T    x3
__device__ __nv_bfloat16 g_w2[(size_t)NLAYER*EMB*3*MLPD]; // w2^T    x3

__device__ __forceinline__ float gelu_f(float x){
    float x3 = x*x*x;
    return 0.5f*x*(1.0f + tanhf(0.7978845608028654f*(x + 0.044715f*x3)));
}

__device__ __forceinline__ uint32_t smem_u32(const void* p){
    uint32_t a;
    asm("{ .reg .u64 t; cvta.to.shared.u64 t, %1; cvt.u32.u64 %0, t; }" : "=r"(a) : "l"(p));
    return a;
}

#define LDSM4(r0,r1,r2,r3, addr) \
    asm volatile("ldmatrix.sync.aligned.m8n8.x4.shared.b16 {%0,%1,%2,%3}, [%4];" \
        : "=r"(r0),"=r"(r1),"=r"(r2),"=r"(r3) : "r"(addr))

#define MMA16816(d, a0,a1,a2,a3, b0,b1) \
    asm volatile("mma.sync.aligned.m16n8k16.row.col.f32.bf16.bf16.f32 " \
        "{%0,%1,%2,%3}, {%4,%5,%6,%7}, {%8,%9}, {%0,%1,%2,%3};" \
        : "+f"((d)[0]),"+f"((d)[1]),"+f"((d)[2]),"+f"((d)[3]) \
        : "r"(a0),"r"(a1),"r"(a2),"r"(a3), "r"(b0),"r"(b1))

#define CPA16(dst, src) \
    asm volatile("cp.async.cg.shared.global [%0], [%1], 16;" :: "r"(dst), "l"(src) : "memory")
#define CPA_COMMIT() asm volatile("cp.async.commit_group;" ::: "memory")
#define CPA_WAIT0()  asm volatile("cp.async.wait_group 0;" ::: "memory")
#define CPA_WAIT1()  asm volatile("cp.async.wait_group 1;" ::: "memory")

// ---------------- tensor-core GEMM (mma.sync bf16, 3-stage cp.async) --------
// stage s: A at s*32768, B at s*32768+16384 ; 3 stages = 98304 B
#define STG_A(s) ((s)*32768)
#define STG_B(s) ((s)*32768 + 16384)
#define SM_TOTAL 98304

__global__ void __launch_bounds__(256,2) tgemm(
    const __nv_bfloat16* __restrict__ A, const __nv_bfloat16* __restrict__ Bt,
    int ldk, int NC,
    float* __restrict__ outf, int ldo, const float* __restrict__ bias,
    __nv_bfloat16* __restrict__ outx3, int epi)
{
    extern __shared__ char dsm[];
    const int tid = threadIdx.x;
    const int wid = tid >> 5;
    const int lane = tid & 31;
    const int warp_m = wid & 1;
    const int warp_n = wid >> 1;
    const int rowBase = blockIdx.y * 128;
    const int colBase = blockIdx.x * 128;
    const uint32_t sbase = smem_u32(dsm);

    const __nv_bfloat16* Ab = A  + (size_t)rowBase * ldk;
    const __nv_bfloat16* Bb = Bt + (size_t)colBase * ldk;

    float acc[4][4][4];
#pragma unroll
    for (int mt=0;mt<4;mt++)
#pragma unroll
      for (int nt=0;nt<4;nt++)
#pragma unroll
        for (int j=0;j<4;j++) acc[mt][nt][j]=0.f;

    const int lA_row = warp_m*64 + (lane & 15);
    const int lA_kb  = (lane >> 4) * 16;
    const int g      = lane >> 3;
    const int lB_row = warp_n*32 + (lane & 7) + (g >> 1) * 8;
    const int lB_kb  = (g & 1) * 16;

    const int ldr_r = tid >> 3;          // base row (0..31), +32 per i
    const int ldr_c = tid & 7;           // 16B column within 128B row

    // prologue: chunks 0 and 1 into stages 0 and 1
#pragma unroll
    for (int i=0;i<4;i++){
        int r = ldr_r + i*32;
        uint32_t off = r*128 + ldr_c*16;
        off ^= (off>>3)&0x70;
        CPA16(sbase + STG_A(0) + off, Ab + (size_t)r*ldk + ldr_c*8);
        CPA16(sbase + STG_B(0) + off, Bb + (size_t)r*ldk + ldr_c*8);
    }
    CPA_COMMIT();
    if (NC > 1){
#pragma unroll
        for (int i=0;i<4;i++){
            int r = ldr_r + i*32;
            uint32_t off = r*128 + ldr_c*16;
            off ^= (off>>3)&0x70;
            CPA16(sbase + STG_A(1) + off, Ab + (size_t)r*ldk + 64 + ldr_c*8);
            CPA16(sbase + STG_B(1) + off, Bb + (size_t)r*ldk + 64 + ldr_c*8);
        }
        CPA_COMMIT();
    }

    int stage = 0;          // stage holding chunk c
    int wstage = 2;         // stage to write chunk c+2 into
    for (int c = 0; c < NC; c++){
        if (c + 2 < NC) CPA_WAIT1(); else CPA_WAIT0();
        __syncthreads();   // chunk c resident for all; stage wstage reads retired

        if (c + 2 < NC){
            int k0 = (c+2)*64;
            uint32_t wa = sbase + STG_A(wstage);
            uint32_t wb = sbase + STG_B(wstage);
#pragma unroll
            for (int i=0;i<4;i++){
                int r = ldr_r + i*32;
                uint32_t off = r*128 + ldr_c*16;
                off ^= (off>>3)&0x70;
                CPA16(wa + off, Ab + (size_t)r*ldk + k0 + ldr_c*8);
                CPA16(wb + off, Bb + (size_t)r*ldk + k0 + ldr_c*8);
            }
            CPA_COMMIT();
        }

        uint32_t sa = sbase + STG_A(stage);
        uint32_t sb = sbase + STG_B(stage);
#pragma unroll
        for (int ks=0; ks<4; ks++){
            uint32_t af[4][4], bf[2][4];
#pragma unroll
            for (int mt=0;mt<4;mt++){
                int row = lA_row + mt*16;
                uint32_t off = row*128 + ks*32 + lA_kb;
                off ^= (off>>3)&0x70;
                LDSM4(af[mt][0],af[mt][1],af[mt][2],af[mt][3], sa + off);
            }
#pragma unroll
            for (int bt=0;bt<2;bt++){
                int row = lB_row + bt*16;
                uint32_t off = row*128 + ks*32 + lB_kb;
                off ^= (off>>3)&0x70;
                LDSM4(bf[bt][0],bf[bt][1],bf[bt][2],bf[bt][3], sb + off);
            }
#pragma unroll
            for (int mt=0;mt<4;mt++)
#pragma unroll
              for (int nt=0;nt<4;nt++){
                  uint32_t b0 = bf[nt>>1][(nt&1)*2];
                  uint32_t b1 = bf[nt>>1][(nt&1)*2+1];
                  MMA16816(acc[mt][nt], af[mt][0],af[mt][1],af[mt][2],af[mt][3], b0,b1);
              }
        }

        stage = (stage + 1 == 3) ? 0 : stage + 1;
        wstage = (wstage + 1 == 3) ? 0 : wstage + 1;
    }
    __syncthreads();

    const int grp = lane >> 2;
    const int thc = (lane & 3) * 2;
#pragma unroll
    for (int mt=0;mt<4;mt++){
#pragma unroll
        for (int half=0; half<2; half++){
            int grow = rowBase + warp_m*64 + mt*16 + grp + half*8;
            if (grow >= ROWS) continue;
#pragma unroll
            for (int nt=0;nt<4;nt++){
                float v0 = acc[mt][nt][half*2+0];
                float v1 = acc[mt][nt][half*2+1];
                int gcol = colBase + warp_n*32 + nt*8 + thc;
                if (epi == 0){
                    float2* p = (float2*)(outf + (size_t)grow*ldo + gcol);
                    *p = make_float2(v0, v1);
                } else if (epi == 1){
                    float2* p = (float2*)(outf + (size_t)grow*EMB + gcol);
                    float2 x = *p;
                    x.x += v0; x.y += v1;
                    *p = x;
                } else if (epi == 2){
                    float t0 = gelu_f(v0 + bias[gcol]);
                    float t1 = gelu_f(v1 + bias[gcol+1]);
                    __nv_bfloat16 h0 = __float2bfloat16(t0);
                    __nv_bfloat16 l0 = __float2bfloat16(t0 - __bfloat162float(h0));
                    __nv_bfloat16 h1 = __float2bfloat16(t1);
                    __nv_bfloat16 l1 = __float2bfloat16(t1 - __bfloat162float(h1));
                    __nv_bfloat16* prow = outx3 + (size_t)grow*3*MLPD;
                    *(__nv_bfloat162*)(prow + gcol)            = __nv_bfloat162(h0,h1);
                    *(__nv_bfloat162*)(prow + MLPD + gcol)     = __nv_bfloat162(l0,l1);
                    *(__nv_bfloat162*)(prow + 2*MLPD + gcol)   = __nv_bfloat162(h0,h1);
                } else {
                    float2* p = (float2*)(outf + (size_t)grow*EMB + gcol);
                    float2 x = *p;
                    x.x += v0 + bias[gcol]; x.y += v1 + bias[gcol+1];
                    *p = x;
                }
            }
        }
    }
}

// ---------------- fused attention, conservative SMEM (59.7 KB) --------------
#define FA_KS 0          /* K region: 197*65 = 12805 floats; later Ps (needs 6400) */
#define FA_QS 12806      /* EVEN base: Q (32*65=2080); later V chunk (32*66=2112) */
#define FA_FLOATS (FA_QS + 2112)   /* 14918 */
#define FA_SMEM (FA_FLOATS*4)      /* 59672 B */

__global__ void __launch_bounds__(256) fattn(const float* __restrict__ qkv,
                                             __nv_bfloat16* __restrict__ ox3)
{
    extern __shared__ float fsm[];
    float* Ks = fsm + FA_KS;
    float* Qs = fsm + FA_QS;
    float* Ps = fsm + FA_KS;   // alias: valid after post-scores barrier (scalar access)
    float* Vs = fsm + FA_QS;   // alias: even base, stride 66 -> float2-aligned
    const int tid = threadIdx.x, wid = tid >> 5, lane = tid & 31;
    const int bh = blockIdx.y;
    const int b = bh / NHEAD, h = bh - b*NHEAD;
    const int q0 = blockIdx.x * 32;
    const float* base = qkv + (size_t)b*SEQ*QKV3 + h*HDIM;

    for (int idx = tid; idx < SEQ*16; idx += 256){
        int r = idx >> 4, c4 = (idx & 15) << 2;
        float4 v = *(const float4*)(base + EMB + (size_t)r*QKV3 + c4);
        float* d = Ks + r*65 + c4;
        d[0]=v.x; d[1]=v.y; d[2]=v.z; d[3]=v.w;
    }
    for (int idx = tid; idx < 32*16; idx += 256){
        int r = idx >> 4, c4 = (idx & 15) << 2;
        int qr = q0 + r;
        float4 v = make_float4(0.f,0.f,0.f,0.f);
        if (qr < SEQ) v = *(const float4*)(base + (size_t)qr*QKV3 + c4);
        float* d = Qs + r*65 + c4;
        d[0]=v.x; d[1]=v.y; d[2]=v.z; d[3]=v.w;
    }
    __syncthreads();

    float s[4][7];
#pragma unroll
    for (int r=0;r<4;r++)
#pragma unroll
      for (int kk=0;kk<7;kk++) s[r][kk]=0.f;

    for (int d0=0; d0<HDIM; d0+=4){
        float q[4][4], k[7][4];
#pragma unroll
        for (int r=0;r<4;r++){
            const float* qp = Qs + (wid*4+r)*65 + d0;
            q[r][0]=qp[0]; q[r][1]=qp[1]; q[r][2]=qp[2]; q[r][3]=qp[3];
        }
#pragma unroll
        for (int kk=0;kk<7;kk++){
            const float* kp = Ks + (lane+32*kk)*65 + d0;
            k[kk][0]=kp[0]; k[kk][1]=kp[1]; k[kk][2]=kp[2]; k[kk][3]=kp[3];
        }
#pragma unroll
        for (int r=0;r<4;r++)
#pragma unroll
          for (int kk=0;kk<7;kk++)
#pragma unroll
            for (int j=0;j<4;j++)
                s[r][kk] += q[r][j]*k[kk][j];
    }

    float invs[4];
#pragma unroll
    for (int r=0;r<4;r++){
        float mx = -1e30f;
#pragma unroll
        for (int kk=0;kk<7;kk++){
            int key = lane + 32*kk;
            s[r][kk] = (key < SEQ) ? s[r][kk]*0.125f : -1e30f;
            mx = fmaxf(mx, s[r][kk]);
        }
#pragma unroll
        for (int o=16;o;o>>=1) mx = fmaxf(mx, __shfl_xor_sync(0xffffffffu, mx, o));
        float sum = 0.f;
#pragma unroll
        for (int kk=0;kk<7;kk++){
            float p = __expf(s[r][kk]-mx);
            s[r][kk] = p; sum += p;
        }
#pragma unroll
        for (int o=16;o;o>>=1) sum += __shfl_xor_sync(0xffffffffu, sum, o);
        invs[r] = 1.f/sum;
    }

    __syncthreads();   // retire all Ks/Qs reads before aliasing

#pragma unroll
    for (int r=0;r<4;r++){
#pragma unroll
        for (int kk=0;kk<7;kk++){
            int key = lane + 32*kk;
            if (key < SEQ) Ps[(wid*4+r)*200 + key] = s[r][kk];
        }
    }

    float o[4][2];
#pragma unroll
    for (int r=0;r<4;r++){ o[r][0]=0.f; o[r][1]=0.f; }

    for (int kt=0; kt<SEQ; kt+=32){
        int nrows = SEQ - kt; if (nrows > 32) nrows = 32;
        __syncthreads();
        for (int idx = tid; idx < nrows*16; idx += 256){
            int r = idx >> 4, c4 = (idx & 15) << 2;
            float4 v = *(const float4*)(base + 2*EMB + (size_t)(kt+r)*QKV3 + c4);
            float* d = Vs + r*66 + c4;
            d[0]=v.x; d[1]=v.y; d[2]=v.z; d[3]=v.w;
        }
        __syncthreads();
        for (int kl=0; kl<nrows; kl++){
            float2 vv = *(float2*)(Vs + kl*66 + lane*2);
#pragma unroll
            for (int r=0;r<4;r++){
                float p = Ps[(wid*4+r)*200 + kt + kl];
                o[r][0] += p*vv.x; o[r][1] += p*vv.y;
            }
        }
    }

#pragma unroll
    for (int r=0;r<4;r++){
        int qr = q0 + wid*4 + r;
        if (qr >= SEQ) continue;
        float v0 = o[r][0]*invs[r], v1 = o[r][1]*invs[r];
        __nv_bfloat16 h0=__float2bfloat16(v0), l0=__float2bfloat16(v0-__bfloat162float(h0));
        __nv_bfloat16 h1=__float2bfloat16(v1), l1=__float2bfloat16(v1-__bfloat162float(h1));
        __nv_bfloat16* orow = ox3 + ((size_t)b*SEQ + qr)*QKV3;
        int col = h*HDIM + lane*2;
        *(__nv_bfloat162*)(orow + col)         = __nv_bfloat162(h0,h1);
        *(__nv_bfloat162*)(orow + EMB + col)   = __nv_bfloat162(l0,l1);
        *(__nv_bfloat162*)(orow + 2*EMB + col) = __nv_bfloat162(h0,h1);
    }
}

// ---------------- weight convert: (L,K,N) fp32 -> (L,N,3K) bf16 [hi|hi|lo] --
__global__ void wconv(const float* __restrict__ src, __nv_bfloat16* __restrict__ dst,
                      int K, int N)
{
    int l = blockIdx.z;
    src += (size_t)l*K*N;
    dst += (size_t)l*N*3*K;
    __shared__ float sm[32][33];
    int k0 = blockIdx.x*32, n0 = blockIdx.y*32;
#pragma unroll
    for (int i=0;i<4;i++){
        int k = k0 + threadIdx.y + i*8;
        sm[threadIdx.y + i*8][threadIdx.x] = src[(size_t)k*N + n0 + threadIdx.x];
    }
    __syncthreads();
#pragma unroll
    for (int i=0;i<4;i++){
        int n = n0 + threadIdx.y + i*8;
        int k = k0 + threadIdx.x;
        float v = sm[threadIdx.x][threadIdx.y + i*8];
        __nv_bfloat16 hi = __float2bfloat16(v);
        __nv_bfloat16 lo = __float2bfloat16(v - __bfloat162float(hi));
        __nv_bfloat16* drow = dst + (size_t)n*3*K;
        drow[k] = hi;
        drow[K + k] = hi;
        drow[2*K + k] = lo;
    }
}

// ---------------- patch-embed GEMM (fp32) -----------------------------------
__global__ __launch_bounds__(256,2) void patch_gemm(
    const float* __restrict__ img, const float* __restrict__ Bw,
    const float* __restrict__ pbias, const float* __restrict__ pos,
    float* __restrict__ X)
{
    __shared__ float As[16][132];
    __shared__ float Bs[16][132];
    const int tid = threadIdx.x;
    const int rowBase = blockIdx.y * 128;
    const int colBase = blockIdx.x * 128;
    const int ty = tid >> 4, tx = tid & 15;

    float acc[2][2][4][4];
#pragma unroll
    for (int a=0;a<2;a++)
#pragma unroll
      for (int b=0;b<2;b++)
#pragma unroll
        for (int i=0;i<4;i++)
#pragma unroll
          for (int j=0;j<4;j++) acc[a][b][i][j]=0.f;

    for (int k0 = 0; k0 < EMB; k0 += 16) {
#pragma unroll
        for (int i=0;i<2;i++){
            int idx = tid + i*256;
            int r = idx >> 2;
            int c4 = (idx & 3) << 2;
            int gr = rowBase + r;
            int gk = k0 + c4;
            int b  = gr / NPATCH;
            int n  = gr - b*NPATCH;
            int pr = n / 14, pc = n - pr*14;
            int ch = gk >> 8;
            int py = (gk >> 4) & 15;
            int px = gk & 15;
            const float* src = img + ((((size_t)(b*3+ch))*224 + pr*16+py)*224 + pc*16 + px);
            float4 v = *(const float4*)src;
            As[c4+0][r]=v.x; As[c4+1][r]=v.y; As[c4+2][r]=v.z; As[c4+3][r]=v.w;
        }
#pragma unroll
        for (int i=0;i<2;i++){
            int idx = tid + i*256;
            int r = idx >> 5;
            int c4 = (idx & 31) << 2;
            *(float4*)&Bs[r][c4] = *(const float4*)(Bw + (size_t)(k0+r)*EMB + colBase + c4);
        }
        __syncthreads();
#pragma unroll
        for (int k=0;k<16;k++){
            float av[2][4], bv[2][4];
            *(float4*)&av[0][0] = *(const float4*)&As[k][ty*4];
            *(float4*)&av[1][0] = *(const float4*)&As[k][ty*4 + 64];
            *(float4*)&bv[0][0] = *(const float4*)&Bs[k][tx*4];
            *(float4*)&bv[1][0] = *(const float4*)&Bs[k][tx*4 + 64];
#pragma unroll
            for (int a=0;a<2;a++)
#pragma unroll
              for (int i=0;i<4;i++)
#pragma unroll
                for (int b=0;b<2;b++)
#pragma unroll
                  for (int j=0;j<4;j++)
                    acc[a][b][i][j] += av[a][i]*bv[b][j];
        }
        __syncthreads();
    }

#pragma unroll
    for (int a=0;a<2;a++){
#pragma unroll
        for (int b=0;b<2;b++){
            int r0 = rowBase + ty*4 + a*64;
            int c0 = colBase + tx*4 + b*64;
#pragma unroll
            for (int i=0;i<4;i++){
                int r = r0 + i;
                int bb = r / NPATCH;
                int n  = r - bb*NPATCH;
                float* Xrow = X + ((size_t)(bb*SEQ) + 1 + n)*EMB + c0;
                const float* prow = pos + (size_t)(1+n)*EMB + c0;
#pragma unroll
                for (int j=0;j<4;j++)
                    Xrow[j] = acc[a][b][i][j] + pbias[c0+j] + prow[j];
            }
        }
    }
}

__global__ void cls_init(const float* __restrict__ cls, const float* __restrict__ pos,
                         float* __restrict__ X)
{
    int idx = blockIdx.x*256 + threadIdx.x;
    if (idx >= BATCH*EMB) return;
    int b = idx / EMB, e = idx - b*EMB;
    X[(size_t)b*SEQ*EMB + e] = cls[e] + pos[e];
}

// ---------------- layernorm -> bf16 x3 [hi|lo|hi] ---------------------------
__global__ void ln_x3(const float* __restrict__ in, __nv_bfloat16* __restrict__ out)
{
    int row = blockIdx.x;
    const float* p = in + (size_t)row*EMB;
    int t = threadIdx.x;
    float v[3]; float s=0.f, s2=0.f;
#pragma unroll
    for (int i=0;i<3;i++){ v[i]=p[t + i*256]; s+=v[i]; s2+=v[i]*v[i]; }
    __shared__ float sh[2][8];
#pragma unroll
    for (int o=16;o;o>>=1){ s += __shfl_xor_sync(0xffffffffu,s,o); s2 += __shfl_xor_sync(0xffffffffu,s2,o); }
    if ((t&31)==0){ sh[0][t>>5]=s; sh[1][t>>5]=s2; }
    __syncthreads();
    if (t < 32){
        s  = (t<8)? sh[0][t] : 0.f;
        s2 = (t<8)? sh[1][t] : 0.f;
#pragma unroll
        for (int o=4;o;o>>=1){ s += __shfl_xor_sync(0xffffffffu,s,o); s2 += __shfl_xor_sync(0xffffffffu,s2,o); }
        if (t==0){ sh[0][0]=s; sh[1][0]=s2; }
    }
    __syncthreads();
    float mu  = sh[0][0]*(1.f/EMB);
    float var = sh[1][0]*(1.f/EMB) - mu*mu;
    float inv = rsqrtf(var + 1e-5f);
    __nv_bfloat16* q = out + (size_t)row*QKV3;
#pragma unroll
    for (int i=0;i<3;i++){
        int e = t + i*256;
        float nv = (v[i]-mu)*inv;
        __nv_bfloat16 hi = __float2bfloat16(nv);
        __nv_bfloat16 lo = __float2bfloat16(nv - __bfloat162float(hi));
        q[e] = hi;
        q[EMB + e] = lo;
        q[2*EMB + e] = hi;
    }
}

__global__ void lnfinal_k(const float* __restrict__ X, const float* __restrict__ g,
                          const float* __restrict__ bta, float* __restrict__ out)
{
    int b = blockIdx.x;
    const float* p = X + (size_t)b*SEQ*EMB;
    int t = threadIdx.x;
    float v[3]; float s=0.f, s2=0.f;
#pragma unroll
    for (int i=0;i<3;i++){ v[i]=p[t + i*256]; s+=v[i]; s2+=v[i]*v[i]; }
    __shared__ float sh[2][8];
#pragma unroll
    for (int o=16;o;o>>=1){ s += __shfl_xor_sync(0xffffffffu,s,o); s2 += __shfl_xor_sync(0xffffffffu,s2,o); }
    if ((t&31)==0){ sh[0][t>>5]=s; sh[1][t>>5]=s2; }
    __syncthreads();
    if (t < 32){
        s  = (t<8)? sh[0][t] : 0.f;
        s2 = (t<8)? sh[1][t] : 0.f;
#pragma unroll
        for (int o=4;o;o>>=1){ s += __shfl_xor_sync(0xffffffffu,s,o); s2 += __shfl_xor_sync(0xffffffffu,s2,o); }
        if (t==0){ sh[0][0]=s; sh[1][0]=s2; }
    }
    __syncthreads();
    float mu  = sh[0][0]*(1.f/EMB);
    float var = sh[1][0]*(1.f/EMB) - mu*mu;
    float inv = rsqrtf(var + 1e-5f);
#pragma unroll
    for (int i=0;i<3;i++){
        int e = t + i*256;
        out[(size_t)b*EMB + e] = (v[i]-mu)*inv*g[e] + bta[e];
    }
}

__global__ void head_k(const float* __restrict__ cls, const float* __restrict__ hw,
                       const float* __restrict__ hb, float* __restrict__ out)
{
    int t = threadIdx.x;
    if (t >= BATCH*10) return;
    int b = t/10, c = t - b*10;
    float s = __ldg(hb + c);
    const float* crow = cls + (size_t)b*EMB;
    for (int e=0;e<EMB;e++) s += crow[e]*__ldg(hw + (size_t)e*10 + c);
    out[t] = s;
}

// ---------------- launch ----------------------------------------------------
extern "C" void kernel_launch(void* const* d_in, const int* in_sizes, int n_in,
                              void* d_out, int out_size)
{
    (void)in_sizes; (void)n_in; (void)out_size;
    const float* img     = (const float*)d_in[0];
    const float* patch_w = (const float*)d_in[1];
    const float* patch_b = (const float*)d_in[2];
    const float* cls_tok = (const float*)d_in[3];
    const float* pos_emb = (const float*)d_in[4];
    const float* qkv_w   = (const float*)d_in[5];
    const float* fc_w    = (const float*)d_in[6];
    const float* mlp_w1  = (const float*)d_in[7];
    const float* mlp_b1  = (const float*)d_in[8];
    const float* mlp_w2  = (const float*)d_in[9];
    const float* mlp_b2  = (const float*)d_in[10];
    const float* ln_g    = (const float*)d_in[11];
    const float* ln_b    = (const float*)d_in[12];
    const float* head_w  = (const float*)d_in[13];
    const float* head_b  = (const float*)d_in[14];
    float* out = (float*)d_out;

    static float *x=nullptr,*qkv=nullptr,*clsb=nullptr;
    static __nv_bfloat16 *hx3=nullptr,*ox3=nullptr,*mx3=nullptr,*wq=nullptr,*wf=nullptr,*w1=nullptr,*w2=nullptr;
    if (!x){
        cudaGetSymbolAddress((void**)&x,    g_x);
        cudaGetSymbolAddress((void**)&qkv,  g_qkv);
        cudaGetSymbolAddress((void**)&clsb, g_cls);
        cudaGetSymbolAddress((void**)&hx3,  g_hx3);
        cudaGetSymbolAddress((void**)&ox3,  g_ox3);
        cudaGetSymbolAddress((void**)&mx3,  g_mx3);
        cudaGetSymbolAddress((void**)&wq,   g_wq);
        cudaGetSymbolAddress((void**)&wf,   g_wf);
        cudaGetSymbolAddress((void**)&w1,   g_w1);
        cudaGetSymbolAddress((void**)&w2,   g_w2);
        cudaFuncSetAttribute(tgemm, cudaFuncAttributeMaxDynamicSharedMemorySize, SM_TOTAL);
        cudaFuncSetAttribute(fattn, cudaFuncAttributeMaxDynamicSharedMemorySize, FA_SMEM);
    }

    // weight split+transpose (bf16 x3), all layers
    wconv<<<dim3(EMB/32,  QKV3/32, NLAYER), dim3(32,8)>>>(qkv_w,  wq, EMB,  QKV3);
    wconv<<<dim3(EMB/32,  EMB/32,  NLAYER), dim3(32,8)>>>(fc_w,   wf, EMB,  EMB);
    wconv<<<dim3(EMB/32,  MLPD/32, NLAYER), dim3(32,8)>>>(mlp_w1, w1, EMB,  MLPD);
    wconv<<<dim3(MLPD/32, EMB/32,  NLAYER), dim3(32,8)>>>(mlp_w2, w2, MLPD, EMB);

    patch_gemm<<<dim3(6,49),256>>>(img, patch_w, patch_b, pos_emb, x);
    cls_init<<<(BATCH*EMB+255)/256,256>>>(cls_tok, pos_emb, x);

    for (int l=0; l<NLAYER; l++){
        ln_x3<<<ROWS,256>>>(x, hx3);
        tgemm<<<dim3(QKV3/128, ROWS_PAD/128), 256, SM_TOTAL>>>(
            hx3, wq + (size_t)l*QKV3*QKV3, QKV3, 36, qkv, QKV3, nullptr, nullptr, 0);
        fattn<<<dim3(7, BHEADS), 256, FA_SMEM>>>(qkv, ox3);
        tgemm<<<dim3(EMB/128, ROWS_PAD/128), 256, SM_TOTAL>>>(
            ox3, wf + (size_t)l*EMB*QKV3, QKV3, 36, x, EMB, nullptr, nullptr, 1);
        ln_x3<<<ROWS,256>>>(x, hx3);
        tgemm<<<dim3(MLPD/128, ROWS_PAD/128), 256, SM_TOTAL>>>(
            hx3, w1 + (size_t)l*MLPD*QKV3, QKV3, 36, nullptr, 0,
            mlp_b1 + (size_t)l*MLPD, mx3, 2);
        tgemm<<<dim3(EMB/128, ROWS_PAD/128), 256, SM_TOTAL>>>(
            mx3, w2 + (size_t)l*EMB*3*MLPD, 3*MLPD, 144, x, EMB,
            mlp_b2 + (size_t)l*EMB, nullptr, 3);
    }

    lnfinal_k<<<BATCH,256>>>(x, ln_g, ln_b, clsb);
    head_k<<<1,512>>>(clsb, head_w, head_b, out);
}

// round 14
// speedup vs baseline: 3.4358x; 1.3156x over previous
#include <cuda_runtime.h>
#include <cuda_fp16.h>
#include <math.h>
#include <stdint.h>

#define BATCH 32
#define SEQ 197
#define EMB 768
#define NHEAD 12
#define HDIM 64
#define QKV3 2304
#define MLPD 3072
#define NLAYER 12
#define ROWS (BATCH*SEQ)      /* 6304 */
#define ROWS_PAD 6400         /* 50*128 */
#define BHEADS (BATCH*NHEAD)  /* 384 */
#define NPATCH 196
#define KX2 (2*EMB)           /* 1536: K' for EMB-input GEMMs */
#define MX2 (2*MLPD)          /* 6144: K' for MLP2 */

// ---------------- scratch (static device globals) ---------------------------
__device__ float g_x[ROWS_PAD*EMB];
__device__ float g_qkv[ROWS_PAD*QKV3];
__device__ float g_cls[BATCH*EMB];
__device__ __half g_hx2[(size_t)ROWS_PAD*KX2];   // LN out, fp16 x2 [hi|lo]
__device__ __half g_ox2[(size_t)ROWS_PAD*KX2];   // attn out, fp16 x2
__device__ __half g_mx2[(size_t)ROWS_PAD*MX2];   // mlp mid, fp16 x2
__device__ __half g_wq[(size_t)NLAYER*QKV3*KX2];  // qkv_w^T [hi|hi]
__device__ __half g_wf[(size_t)NLAYER*EMB*KX2];   // fc_w^T  [hi|hi]
__device__ __half g_w1[(size_t)NLAYER*MLPD*KX2];  // w1^T    [hi|hi]
__device__ __half g_w2[(size_t)NLAYER*EMB*MX2];   // w2^T    [hi|hi]

__device__ __forceinline__ float gelu_f(float x){
    float x3 = x*x*x;
    return 0.5f*x*(1.0f + tanhf(0.7978845608028654f*(x + 0.044715f*x3)));
}

__device__ __forceinline__ uint32_t smem_u32(const void* p){
    uint32_t a;
    asm("{ .reg .u64 t; cvta.to.shared.u64 t, %1; cvt.u32.u64 %0, t; }" : "=r"(a) : "l"(p));
    return a;
}

#define LDSM4(r0,r1,r2,r3, addr) \
    asm volatile("ldmatrix.sync.aligned.m8n8.x4.shared.b16 {%0,%1,%2,%3}, [%4];" \
        : "=r"(r0),"=r"(r1),"=r"(r2),"=r"(r3) : "r"(addr))

#define MMA16816(d, a0,a1,a2,a3, b0,b1) \
    asm volatile("mma.sync.aligned.m16n8k16.row.col.f32.f16.f16.f32 " \
        "{%0,%1,%2,%3}, {%4,%5,%6,%7}, {%8,%9}, {%0,%1,%2,%3};" \
        : "+f"((d)[0]),"+f"((d)[1]),"+f"((d)[2]),"+f"((d)[3]) \
        : "r"(a0),"r"(a1),"r"(a2),"r"(a3), "r"(b0),"r"(b1))

#define CPA16(dst, src) \
    asm volatile("cp.async.cg.shared.global [%0], [%1], 16;" :: "r"(dst), "l"(src) : "memory")
#define CPA_COMMIT() asm volatile("cp.async.commit_group;" ::: "memory")
#define CPA_WAIT0()  asm volatile("cp.async.wait_group 0;" ::: "memory")
#define CPA_WAIT1()  asm volatile("cp.async.wait_group 1;" ::: "memory")

// ---------------- tensor-core GEMM (mma.sync fp16, 3-stage cp.async) --------
#define STG_A(s) ((s)*32768)
#define STG_B(s) ((s)*32768 + 16384)
#define SM_TOTAL 98304

__global__ void __launch_bounds__(256,2) tgemm(
    const __half* __restrict__ A, const __half* __restrict__ Bt,
    int ldk, int NC,
    float* __restrict__ outf, int ldo, const float* __restrict__ bias,
    __half* __restrict__ outx2, int epi)
{
    extern __shared__ char dsm[];
    const int tid = threadIdx.x;
    const int wid = tid >> 5;
    const int lane = tid & 31;
    const int warp_m = wid & 1;
    const int warp_n = wid >> 1;
    const int rowBase = blockIdx.y * 128;
    const int colBase = blockIdx.x * 128;
    const uint32_t sbase = smem_u32(dsm);

    const __half* Ab = A  + (size_t)rowBase * ldk;
    const __half* Bb = Bt + (size_t)colBase * ldk;

    float acc[4][4][4];
#pragma unroll
    for (int mt=0;mt<4;mt++)
#pragma unroll
      for (int nt=0;nt<4;nt++)
#pragma unroll
        for (int j=0;j<4;j++) acc[mt][nt][j]=0.f;

    const int lA_row = warp_m*64 + (lane & 15);
    const int lA_kb  = (lane >> 4) * 16;
    const int g      = lane >> 3;
    const int lB_row = warp_n*32 + (lane & 7) + (g >> 1) * 8;
    const int lB_kb  = (g & 1) * 16;

    const int ldr_r = tid >> 3;
    const int ldr_c = tid & 7;

    // prologue: chunks 0 and 1 into stages 0 and 1
#pragma unroll
    for (int i=0;i<4;i++){
        int r = ldr_r + i*32;
        uint32_t off = r*128 + ldr_c*16;
        off ^= (off>>3)&0x70;
        CPA16(sbase + STG_A(0) + off, Ab + (size_t)r*ldk + ldr_c*8);
        CPA16(sbase + STG_B(0) + off, Bb + (size_t)r*ldk + ldr_c*8);
    }
    CPA_COMMIT();
    if (NC > 1){
#pragma unroll
        for (int i=0;i<4;i++){
            int r = ldr_r + i*32;
            uint32_t off = r*128 + ldr_c*16;
            off ^= (off>>3)&0x70;
            CPA16(sbase + STG_A(1) + off, Ab + (size_t)r*ldk + 64 + ldr_c*8);
            CPA16(sbase + STG_B(1) + off, Bb + (size_t)r*ldk + 64 + ldr_c*8);
        }
        CPA_COMMIT();
    }

    int stage = 0;
    int wstage = 2;
    for (int c = 0; c < NC; c++){
        if (c + 2 < NC) CPA_WAIT1(); else CPA_WAIT0();
        __syncthreads();

        if (c + 2 < NC){
            int k0 = (c+2)*64;
            uint32_t wa = sbase + STG_A(wstage);
            uint32_t wb = sbase + STG_B(wstage);
#pragma unroll
            for (int i=0;i<4;i++){
                int r = ldr_r + i*32;
                uint32_t off = r*128 + ldr_c*16;
                off ^= (off>>3)&0x70;
                CPA16(wa + off, Ab + (size_t)r*ldk + k0 + ldr_c*8);
                CPA16(wb + off, Bb + (size_t)r*ldk + k0 + ldr_c*8);
            }
            CPA_COMMIT();
        }

        uint32_t sa = sbase + STG_A(stage);
        uint32_t sb = sbase + STG_B(stage);
#pragma unroll
        for (int ks=0; ks<4; ks++){
            uint32_t af[4][4], bf[2][4];
#pragma unroll
            for (int mt=0;mt<4;mt++){
                int row = lA_row + mt*16;
                uint32_t off = row*128 + ks*32 + lA_kb;
                off ^= (off>>3)&0x70;
                LDSM4(af[mt][0],af[mt][1],af[mt][2],af[mt][3], sa + off);
            }
#pragma unroll
            for (int bt=0;bt<2;bt++){
                int row = lB_row + bt*16;
                uint32_t off = row*128 + ks*32 + lB_kb;
                off ^= (off>>3)&0x70;
                LDSM4(bf[bt][0],bf[bt][1],bf[bt][2],bf[bt][3], sb + off);
            }
#pragma unroll
            for (int mt=0;mt<4;mt++)
#pragma unroll
              for (int nt=0;nt<4;nt++){
                  uint32_t b0 = bf[nt>>1][(nt&1)*2];
                  uint32_t b1 = bf[nt>>1][(nt&1)*2+1];
                  MMA16816(acc[mt][nt], af[mt][0],af[mt][1],af[mt][2],af[mt][3], b0,b1);
              }
        }

        stage = (stage + 1 == 3) ? 0 : stage + 1;
        wstage = (wstage + 1 == 3) ? 0 : wstage + 1;
    }
    __syncthreads();

    const int grp = lane >> 2;
    const int thc = (lane & 3) * 2;
#pragma unroll
    for (int mt=0;mt<4;mt++){
#pragma unroll
        for (int half=0; half<2; half++){
            int grow = rowBase + warp_m*64 + mt*16 + grp + half*8;
            if (grow >= ROWS) continue;
#pragma unroll
            for (int nt=0;nt<4;nt++){
                float v0 = acc[mt][nt][half*2+0];
                float v1 = acc[mt][nt][half*2+1];
                int gcol = colBase + warp_n*32 + nt*8 + thc;
                if (epi == 0){
                    float2* p = (float2*)(outf + (size_t)grow*ldo + gcol);
                    *p = make_float2(v0, v1);
                } else if (epi == 1){
                    float2* p = (float2*)(outf + (size_t)grow*EMB + gcol);
                    float2 x = *p;
                    x.x += v0; x.y += v1;
                    *p = x;
                } else if (epi == 2){
                    float t0 = gelu_f(v0 + bias[gcol]);
                    float t1 = gelu_f(v1 + bias[gcol+1]);
                    __half h0 = __float2half_rn(t0);
                    __half l0 = __float2half_rn(t0 - __half2float(h0));
                    __half h1 = __float2half_rn(t1);
                    __half l1 = __float2half_rn(t1 - __half2float(h1));
                    __half* prow = outx2 + (size_t)grow*MX2;
                    __half2 hh; hh.x = h0; hh.y = h1;
                    __half2 ll; ll.x = l0; ll.y = l1;
                    *(__half2*)(prow + gcol)        = hh;
                    *(__half2*)(prow + MLPD + gcol) = ll;
                } else {
                    float2* p = (float2*)(outf + (size_t)grow*EMB + gcol);
                    float2 x = *p;
                    x.x += v0 + bias[gcol]; x.y += v1 + bias[gcol+1];
                    *p = x;
                }
            }
        }
    }
}

// ---------------- fused attention, conservative SMEM (59.7 KB) --------------
#define FA_KS 0
#define FA_QS 12806
#define FA_FLOATS (FA_QS + 2112)
#define FA_SMEM (FA_FLOATS*4)

__global__ void __launch_bounds__(256) fattn(const float* __restrict__ qkv,
                                             __half* __restrict__ ox2)
{
    extern __shared__ float fsm[];
    float* Ks = fsm + FA_KS;
    float* Qs = fsm + FA_QS;
    float* Ps = fsm + FA_KS;
    float* Vs = fsm + FA_QS;
    const int tid = threadIdx.x, wid = tid >> 5, lane = tid & 31;
    const int bh = blockIdx.y;
    const int b = bh / NHEAD, h = bh - b*NHEAD;
    const int q0 = blockIdx.x * 32;
    const float* base = qkv + (size_t)b*SEQ*QKV3 + h*HDIM;

    for (int idx = tid; idx < SEQ*16; idx += 256){
        int r = idx >> 4, c4 = (idx & 15) << 2;
        float4 v = *(const float4*)(base + EMB + (size_t)r*QKV3 + c4);
        float* d = Ks + r*65 + c4;
        d[0]=v.x; d[1]=v.y; d[2]=v.z; d[3]=v.w;
    }
    for (int idx = tid; idx < 32*16; idx += 256){
        int r = idx >> 4, c4 = (idx & 15) << 2;
        int qr = q0 + r;
        float4 v = make_float4(0.f,0.f,0.f,0.f);
        if (qr < SEQ) v = *(const float4*)(base + (size_t)qr*QKV3 + c4);
        float* d = Qs + r*65 + c4;
        d[0]=v.x; d[1]=v.y; d[2]=v.z; d[3]=v.w;
    }
    __syncthreads();

    float s[4][7];
#pragma unroll
    for (int r=0;r<4;r++)
#pragma unroll
      for (int kk=0;kk<7;kk++) s[r][kk]=0.f;

    for (int d0=0; d0<HDIM; d0+=4){
        float q[4][4], k[7][4];
#pragma unroll
        for (int r=0;r<4;r++){
            const float* qp = Qs + (wid*4+r)*65 + d0;
            q[r][0]=qp[0]; q[r][1]=qp[1]; q[r][2]=qp[2]; q[r][3]=qp[3];
        }
#pragma unroll
        for (int kk=0;kk<7;kk++){
            const float* kp = Ks + (lane+32*kk)*65 + d0;
            k[kk][0]=kp[0]; k[kk][1]=kp[1]; k[kk][2]=kp[2]; k[kk][3]=kp[3];
        }
#pragma unroll
        for (int r=0;r<4;r++)
#pragma unroll
          for (int kk=0;kk<7;kk++)
#pragma unroll
            for (int j=0;j<4;j++)
                s[r][kk] += q[r][j]*k[kk][j];
    }

    float invs[4];
#pragma unroll
    for (int r=0;r<4;r++){
        float mx = -1e30f;
#pragma unroll
        for (int kk=0;kk<7;kk++){
            int key = lane + 32*kk;
            s[r][kk] = (key < SEQ) ? s[r][kk]*0.125f : -1e30f;
            mx = fmaxf(mx, s[r][kk]);
        }
#pragma unroll
        for (int o=16;o;o>>=1) mx = fmaxf(mx, __shfl_xor_sync(0xffffffffu, mx, o));
        float sum = 0.f;
#pragma unroll
        for (int kk=0;kk<7;kk++){
            float p = __expf(s[r][kk]-mx);
            s[r][kk] = p; sum += p;
        }
#pragma unroll
        for (int o=16;o;o>>=1) sum += __shfl_xor_sync(0xffffffffu, sum, o);
        invs[r] = 1.f/sum;
    }

    __syncthreads();

#pragma unroll
    for (int r=0;r<4;r++){
#pragma unroll
        for (int kk=0;kk<7;kk++){
            int key = lane + 32*kk;
            if (key < SEQ) Ps[(wid*4+r)*200 + key] = s[r][kk];
        }
    }

    float o[4][2];
#pragma unroll
    for (int r=0;r<4;r++){ o[r][0]=0.f; o[r][1]=0.f; }

    for (int kt=0; kt<SEQ; kt+=32){
        int nrows = SEQ - kt; if (nrows > 32) nrows = 32;
        __syncthreads();
        for (int idx = tid; idx < nrows*16; idx += 256){
            int r = idx >> 4, c4 = (idx & 15) << 2;
            float4 v = *(const float4*)(base + 2*EMB + (size_t)(kt+r)*QKV3 + c4);
            float* d = Vs + r*66 + c4;
            d[0]=v.x; d[1]=v.y; d[2]=v.z; d[3]=v.w;
        }
        __syncthreads();
        for (int kl=0; kl<nrows; kl++){
            float2 vv = *(float2*)(Vs + kl*66 + lane*2);
#pragma unroll
            for (int r=0;r<4;r++){
                float p = Ps[(wid*4+r)*200 + kt + kl];
                o[r][0] += p*vv.x; o[r][1] += p*vv.y;
            }
        }
    }

#pragma unroll
    for (int r=0;r<4;r++){
        int qr = q0 + wid*4 + r;
        if (qr >= SEQ) continue;
        float v0 = o[r][0]*invs[r], v1 = o[r][1]*invs[r];
        __half h0=__float2half_rn(v0), l0=__float2half_rn(v0-__half2float(h0));
        __half h1=__float2half_rn(v1), l1=__float2half_rn(v1-__half2float(h1));
        __half* orow = ox2 + ((size_t)b*SEQ + qr)*KX2;
        int col = h*HDIM + lane*2;
        __half2 hh; hh.x=h0; hh.y=h1;
        __half2 ll; ll.x=l0; ll.y=l1;
        *(__half2*)(orow + col)       = hh;
        *(__half2*)(orow + EMB + col) = ll;
    }
}

// ---------------- weight convert: (L,K,N) fp32 -> (L,N,2K) fp16 [hi|hi] -----
__global__ void wconv(const float* __restrict__ src, __half* __restrict__ dst,
                      int K, int N)
{
    int l = blockIdx.z;
    src += (size_t)l*K*N;
    dst += (size_t)l*N*2*K;
    __shared__ float sm[32][33];
    int k0 = blockIdx.x*32, n0 = blockIdx.y*32;
#pragma unroll
    for (int i=0;i<4;i++){
        int k = k0 + threadIdx.y + i*8;
        sm[threadIdx.y + i*8][threadIdx.x] = src[(size_t)k*N + n0 + threadIdx.x];
    }
    __syncthreads();
#pragma unroll
    for (int i=0;i<4;i++){
        int n = n0 + threadIdx.y + i*8;
        int k = k0 + threadIdx.x;
        float v = sm[threadIdx.x][threadIdx.y + i*8];
        __half hi = __float2half_rn(v);
        __half* drow = dst + (size_t)n*2*K;
        drow[k] = hi;
        drow[K + k] = hi;
    }
}

// ---------------- patch-embed GEMM (fp32) -----------------------------------
__global__ __launch_bounds__(256,2) void patch_gemm(
    const float* __restrict__ img, const float* __restrict__ Bw,
    const float* __restrict__ pbias, const float* __restrict__ pos,
    float* __restrict__ X)
{
    __shared__ float As[16][132];
    __shared__ float Bs[16][132];
    const int tid = threadIdx.x;
    const int rowBase = blockIdx.y * 128;
    const int colBase = blockIdx.x * 128;
    const int ty = tid >> 4, tx = tid & 15;

    float acc[2][2][4][4];
#pragma unroll
    for (int a=0;a<2;a++)
#pragma unroll
      for (int b=0;b<2;b++)
#pragma unroll
        for (int i=0;i<4;i++)
#pragma unroll
          for (int j=0;j<4;j++) acc[a][b][i][j]=0.f;

    for (int k0 = 0; k0 < EMB; k0 += 16) {
#pragma unroll
        for (int i=0;i<2;i++){
            int idx = tid + i*256;
            int r = idx >> 2;
            int c4 = (idx & 3) << 2;
            int gr = rowBase + r;
            int gk = k0 + c4;
            int b  = gr / NPATCH;
            int n  = gr - b*NPATCH;
            int pr = n / 14, pc = n - pr*14;
            int ch = gk >> 8;
            int py = (gk >> 4) & 15;
            int px = gk & 15;
            const float* src = img + ((((size_t)(b*3+ch))*224 + pr*16+py)*224 + pc*16 + px);
            float4 v = *(const float4*)src;
            As[c4+0][r]=v.x; As[c4+1][r]=v.y; As[c4+2][r]=v.z; As[c4+3][r]=v.w;
        }
#pragma unroll
        for (int i=0;i<2;i++){
            int idx = tid + i*256;
            int r = idx >> 5;
            int c4 = (idx & 31) << 2;
            *(float4*)&Bs[r][c4] = *(const float4*)(Bw + (size_t)(k0+r)*EMB + colBase + c4);
        }
        __syncthreads();
#pragma unroll
        for (int k=0;k<16;k++){
            float av[2][4], bv[2][4];
            *(float4*)&av[0][0] = *(const float4*)&As[k][ty*4];
            *(float4*)&av[1][0] = *(const float4*)&As[k][ty*4 + 64];
            *(float4*)&bv[0][0] = *(const float4*)&Bs[k][tx*4];
            *(float4*)&bv[1][0] = *(const float4*)&Bs[k][tx*4 + 64];
#pragma unroll
            for (int a=0;a<2;a++)
#pragma unroll
              for (int i=0;i<4;i++)
#pragma unroll
                for (int b=0;b<2;b++)
#pragma unroll
                  for (int j=0;j<4;j++)
                    acc[a][b][i][j] += av[a][i]*bv[b][j];
        }
        __syncthreads();
    }

#pragma unroll
    for (int a=0;a<2;a++){
#pragma unroll
        for (int b=0;b<2;b++){
            int r0 = rowBase + ty*4 + a*64;
            int c0 = colBase + tx*4 + b*64;
#pragma unroll
            for (int i=0;i<4;i++){
                int r = r0 + i;
                int bb = r / NPATCH;
                int n  = r - bb*NPATCH;
                float* Xrow = X + ((size_t)(bb*SEQ) + 1 + n)*EMB + c0;
                const float* prow = pos + (size_t)(1+n)*EMB + c0;
#pragma unroll
                for (int j=0;j<4;j++)
                    Xrow[j] = acc[a][b][i][j] + pbias[c0+j] + prow[j];
            }
        }
    }
}

__global__ void cls_init(const float* __restrict__ cls, const float* __restrict__ pos,
                         float* __restrict__ X)
{
    int idx = blockIdx.x*256 + threadIdx.x;
    if (idx >= BATCH*EMB) return;
    int b = idx / EMB, e = idx - b*EMB;
    X[(size_t)b*SEQ*EMB + e] = cls[e] + pos[e];
}

// ---------------- layernorm -> fp16 x2 [hi|lo] ------------------------------
__global__ void ln_x2(const float* __restrict__ in, __half* __restrict__ out)
{
    int row = blockIdx.x;
    const float* p = in + (size_t)row*EMB;
    int t = threadIdx.x;
    float v[3]; float s=0.f, s2=0.f;
#pragma unroll
    for (int i=0;i<3;i++){ v[i]=p[t + i*256]; s+=v[i]; s2+=v[i]*v[i]; }
    __shared__ float sh[2][8];
#pragma unroll
    for (int o=16;o;o>>=1){ s += __shfl_xor_sync(0xffffffffu,s,o); s2 += __shfl_xor_sync(0xffffffffu,s2,o); }
    if ((t&31)==0){ sh[0][t>>5]=s; sh[1][t>>5]=s2; }
    __syncthreads();
    if (t < 32){
        s  = (t<8)? sh[0][t] : 0.f;
        s2 = (t<8)? sh[1][t] : 0.f;
#pragma unroll
        for (int o=4;o;o>>=1){ s += __shfl_xor_sync(0xffffffffu,s,o); s2 += __shfl_xor_sync(0xffffffffu,s2,o); }
        if (t==0){ sh[0][0]=s; sh[1][0]=s2; }
    }
    __syncthreads();
    float mu  = sh[0][0]*(1.f/EMB);
    float var = sh[1][0]*(1.f/EMB) - mu*mu;
    float inv = rsqrtf(var + 1e-5f);
    __half* q = out + (size_t)row*KX2;
#pragma unroll
    for (int i=0;i<3;i++){
        int e = t + i*256;
        float nv = (v[i]-mu)*inv;
        __half hi = __float2half_rn(nv);
        __half lo = __float2half_rn(nv - __half2float(hi));
        q[e] = hi;
        q[EMB + e] = lo;
    }
}

__global__ void lnfinal_k(const float* __restrict__ X, const float* __restrict__ g,
                          const float* __restrict__ bta, float* __restrict__ out)
{
    int b = blockIdx.x;
    const float* p = X + (size_t)b*SEQ*EMB;
    int t = threadIdx.x;
    float v[3]; float s=0.f, s2=0.f;
#pragma unroll
    for (int i=0;i<3;i++){ v[i]=p[t + i*256]; s+=v[i]; s2+=v[i]*v[i]; }
    __shared__ float sh[2][8];
#pragma unroll
    for (int o=16;o;o>>=1){ s += __shfl_xor_sync(0xffffffffu,s,o); s2 += __shfl_xor_sync(0xffffffffu,s2,o); }
    if ((t&31)==0){ sh[0][t>>5]=s; sh[1][t>>5]=s2; }
    __syncthreads();
    if (t < 32){
        s  = (t<8)? sh[0][t] : 0.f;
        s2 = (t<8)? sh[1][t] : 0.f;
#pragma unroll
        for (int o=4;o;o>>=1){ s += __shfl_xor_sync(0xffffffffu,s,o); s2 += __shfl_xor_sync(0xffffffffu,s2,o); }
        if (t==0){ sh[0][0]=s; sh[1][0]=s2; }
    }
    __syncthreads();
    float mu  = sh[0][0]*(1.f/EMB);
    float var = sh[1][0]*(1.f/EMB) - mu*mu;
    float inv = rsqrtf(var + 1e-5f);
#pragma unroll
    for (int i=0;i<3;i++){
        int e = t + i*256;
        out[(size_t)b*EMB + e] = (v[i]-mu)*inv*g[e] + bta[e];
    }
}

__global__ void head_k(const float* __restrict__ cls, const float* __restrict__ hw,
                       const float* __restrict__ hb, float* __restrict__ out)
{
    int t = threadIdx.x;
    if (t >= BATCH*10) return;
    int b = t/10, c = t - b*10;
    float s = __ldg(hb + c);
    const float* crow = cls + (size_t)b*EMB;
    for (int e=0;e<EMB;e++) s += crow[e]*__ldg(hw + (size_t)e*10 + c);
    out[t] = s;
}

// ---------------- launch ----------------------------------------------------
extern "C" void kernel_launch(void* const* d_in, const int* in_sizes, int n_in,
                              void* d_out, int out_size)
{
    (void)in_sizes; (void)n_in; (void)out_size;
    const float* img     = (const float*)d_in[0];
    const float* patch_w = (const float*)d_in[1];
    const float* patch_b = (const float*)d_in[2];
    const float* cls_tok = (const float*)d_in[3];
    const float* pos_emb = (const float*)d_in[4];
    const float* qkv_w   = (const float*)d_in[5];
    const float* fc_w    = (const float*)d_in[6];
    const float* mlp_w1  = (const float*)d_in[7];
    const float* mlp_b1  = (const float*)d_in[8];
    const float* mlp_w2  = (const float*)d_in[9];
    const float* mlp_b2  = (const float*)d_in[10];
    const float* ln_g    = (const float*)d_in[11];
    const float* ln_b    = (const float*)d_in[12];
    const float* head_w  = (const float*)d_in[13];
    const float* head_b  = (const float*)d_in[14];
    float* out = (float*)d_out;

    static float *x=nullptr,*qkv=nullptr,*clsb=nullptr;
    static __half *hx2=nullptr,*ox2=nullptr,*mx2=nullptr,*wq=nullptr,*wf=nullptr,*w1=nullptr,*w2=nullptr;
    if (!x){
        cudaGetSymbolAddress((void**)&x,    g_x);
        cudaGetSymbolAddress((void**)&qkv,  g_qkv);
        cudaGetSymbolAddress((void**)&clsb, g_cls);
        cudaGetSymbolAddress((void**)&hx2,  g_hx2);
        cudaGetSymbolAddress((void**)&ox2,  g_ox2);
        cudaGetSymbolAddress((void**)&mx2,  g_mx2);
        cudaGetSymbolAddress((void**)&wq,   g_wq);
        cudaGetSymbolAddress((void**)&wf,   g_wf);
        cudaGetSymbolAddress((void**)&w1,   g_w1);
        cudaGetSymbolAddress((void**)&w2,   g_w2);
        cudaFuncSetAttribute(tgemm, cudaFuncAttributeMaxDynamicSharedMemorySize, SM_TOTAL);
        cudaFuncSetAttribute(fattn, cudaFuncAttributeMaxDynamicSharedMemorySize, FA_SMEM);
    }

    // weight convert (fp16 [hi|hi]), all layers
    wconv<<<dim3(EMB/32,  QKV3/32, NLAYER), dim3(32,8)>>>(qkv_w,  wq, EMB,  QKV3);
    wconv<<<dim3(EMB/32,  EMB/32,  NLAYER), dim3(32,8)>>>(fc_w,   wf, EMB,  EMB);
    wconv<<<dim3(EMB/32,  MLPD/32, NLAYER), dim3(32,8)>>>(mlp_w1, w1, EMB,  MLPD);
    wconv<<<dim3(MLPD/32, EMB/32,  NLAYER), dim3(32,8)>>>(mlp_w2, w2, MLPD, EMB);

    patch_gemm<<<dim3(6,49),256>>>(img, patch_w, patch_b, pos_emb, x);
    cls_init<<<(BATCH*EMB+255)/256,256>>>(cls_tok, pos_emb, x);

    for (int l=0; l<NLAYER; l++){
        ln_x2<<<ROWS,256>>>(x, hx2);
        tgemm<<<dim3(QKV3/128, ROWS_PAD/128), 256, SM_TOTAL>>>(
            hx2, wq + (size_t)l*QKV3*KX2, KX2, 24, qkv, QKV3, nullptr, nullptr, 0);
        fattn<<<dim3(7, BHEADS), 256, FA_SMEM>>>(qkv, ox2);
        tgemm<<<dim3(EMB/128, ROWS_PAD/128), 256, SM_TOTAL>>>(
            ox2, wf + (size_t)l*EMB*KX2, KX2, 24, x, EMB, nullptr, nullptr, 1);
        ln_x2<<<ROWS,256>>>(x, hx2);
        tgemm<<<dim3(MLPD/128, ROWS_PAD/128), 256, SM_TOTAL>>>(
            hx2, w1 + (size_t)l*MLPD*KX2, KX2, 24, nullptr, 0,
            mlp_b1 + (size_t)l*MLPD, mx2, 2);
        tgemm<<<dim3(EMB/128, ROWS_PAD/128), 256, SM_TOTAL>>>(
            mx2, w2 + (size_t)l*EMB*MX2, MX2, 96, x, EMB,
            mlp_b2 + (size_t)l*EMB, nullptr, 3);
    }

    lnfinal_k<<<BATCH,256>>>(x, ln_g, ln_b, clsb);
    head_k<<<1,512>>>(clsb, head_w, head_b, out);
}

// round 15
// speedup vs baseline: 4.9972x; 1.4544x over previous
#include <cuda_runtime.h>
#include <cuda_fp16.h>
#include <math.h>
#include <stdint.h>

#define BATCH 32
#define SEQ 197
#define EMB 768
#define NHEAD 12
#define HDIM 64
#define QKV3 2304
#define MLPD 3072
#define NLAYER 12
#define ROWS (BATCH*SEQ)      /* 6304 */
#define ROWS_PAD 6400         /* 50*128 */
#define BHEADS (BATCH*NHEAD)  /* 384 */
#define NPATCH 196

// ---------------- scratch (static device globals) ---------------------------
__device__ float g_x[ROWS_PAD*EMB];
__device__ float g_qkv[ROWS_PAD*QKV3];
__device__ float g_cls[BATCH*EMB];
__device__ __half g_hx1[(size_t)ROWS_PAD*EMB];    // LN out, fp16
__device__ __half g_ox1[(size_t)ROWS_PAD*EMB];    // attn out, fp16
__device__ __half g_mx1[(size_t)ROWS_PAD*MLPD];   // mlp mid, fp16
__device__ __half g_wq[(size_t)NLAYER*QKV3*EMB];  // qkv_w^T fp16
__device__ __half g_wf[(size_t)NLAYER*EMB*EMB];   // fc_w^T  fp16
__device__ __half g_w1[(size_t)NLAYER*MLPD*EMB];  // w1^T    fp16
__device__ __half g_w2[(size_t)NLAYER*EMB*MLPD];  // w2^T    fp16

__device__ __forceinline__ float gelu_f(float x){
    float x3 = x*x*x;
    return 0.5f*x*(1.0f + tanhf(0.7978845608028654f*(x + 0.044715f*x3)));
}

__device__ __forceinline__ uint32_t smem_u32(const void* p){
    uint32_t a;
    asm("{ .reg .u64 t; cvta.to.shared.u64 t, %1; cvt.u32.u64 %0, t; }" : "=r"(a) : "l"(p));
    return a;
}

#define LDSM4(r0,r1,r2,r3, addr) \
    asm volatile("ldmatrix.sync.aligned.m8n8.x4.shared.b16 {%0,%1,%2,%3}, [%4];" \
        : "=r"(r0),"=r"(r1),"=r"(r2),"=r"(r3) : "r"(addr))

#define MMA16816(d, a0,a1,a2,a3, b0,b1) \
    asm volatile("mma.sync.aligned.m16n8k16.row.col.f32.f16.f16.f32 " \
        "{%0,%1,%2,%3}, {%4,%5,%6,%7}, {%8,%9}, {%0,%1,%2,%3};" \
        : "+f"((d)[0]),"+f"((d)[1]),"+f"((d)[2]),"+f"((d)[3]) \
        : "r"(a0),"r"(a1),"r"(a2),"r"(a3), "r"(b0),"r"(b1))

#define CPA16(dst, src) \
    asm volatile("cp.async.cg.shared.global [%0], [%1], 16;" :: "r"(dst), "l"(src) : "memory")
#define CPA_COMMIT() asm volatile("cp.async.commit_group;" ::: "memory")
#define CPA_WAIT0()  asm volatile("cp.async.wait_group 0;" ::: "memory")
#define CPA_WAIT1()  asm volatile("cp.async.wait_group 1;" ::: "memory")

// ---------------- tensor-core GEMM (mma.sync fp16, 3-stage cp.async) --------
#define STG_A(s) ((s)*32768)
#define STG_B(s) ((s)*32768 + 16384)
#define SM_TOTAL 98304

__global__ void __launch_bounds__(256,2) tgemm(
    const __half* __restrict__ A, const __half* __restrict__ Bt,
    int ldk, int NC,
    float* __restrict__ outf, int ldo, const float* __restrict__ bias,
    __half* __restrict__ outx1, int epi)
{
    extern __shared__ char dsm[];
    const int tid = threadIdx.x;
    const int wid = tid >> 5;
    const int lane = tid & 31;
    const int warp_m = wid & 1;
    const int warp_n = wid >> 1;
    const int rowBase = blockIdx.y * 128;
    const int colBase = blockIdx.x * 128;
    const uint32_t sbase = smem_u32(dsm);

    const __half* Ab = A  + (size_t)rowBase * ldk;
    const __half* Bb = Bt + (size_t)colBase * ldk;

    float acc[4][4][4];
#pragma unroll
    for (int mt=0;mt<4;mt++)
#pragma unroll
      for (int nt=0;nt<4;nt++)
#pragma unroll
        for (int j=0;j<4;j++) acc[mt][nt][j]=0.f;

    const int lA_row = warp_m*64 + (lane & 15);
    const int lA_kb  = (lane >> 4) * 16;
    const int g      = lane >> 3;
    const int lB_row = warp_n*32 + (lane & 7) + (g >> 1) * 8;
    const int lB_kb  = (g & 1) * 16;

    const int ldr_r = tid >> 3;
    const int ldr_c = tid & 7;

    // prologue: chunks 0 and 1 into stages 0 and 1
#pragma unroll
    for (int i=0;i<4;i++){
        int r = ldr_r + i*32;
        uint32_t off = r*128 + ldr_c*16;
        off ^= (off>>3)&0x70;
        CPA16(sbase + STG_A(0) + off, Ab + (size_t)r*ldk + ldr_c*8);
        CPA16(sbase + STG_B(0) + off, Bb + (size_t)r*ldk + ldr_c*8);
    }
    CPA_COMMIT();
    if (NC > 1){
#pragma unroll
        for (int i=0;i<4;i++){
            int r = ldr_r + i*32;
            uint32_t off = r*128 + ldr_c*16;
            off ^= (off>>3)&0x70;
            CPA16(sbase + STG_A(1) + off, Ab + (size_t)r*ldk + 64 + ldr_c*8);
            CPA16(sbase + STG_B(1) + off, Bb + (size_t)r*ldk + 64 + ldr_c*8);
        }
        CPA_COMMIT();
    }

    int stage = 0;
    int wstage = 2;
    for (int c = 0; c < NC; c++){
        if (c + 2 < NC) CPA_WAIT1(); else CPA_WAIT0();
        __syncthreads();

        if (c + 2 < NC){
            int k0 = (c+2)*64;
            uint32_t wa = sbase + STG_A(wstage);
            uint32_t wb = sbase + STG_B(wstage);
#pragma unroll
            for (int i=0;i<4;i++){
                int r = ldr_r + i*32;
                uint32_t off = r*128 + ldr_c*16;
                off ^= (off>>3)&0x70;
                CPA16(wa + off, Ab + (size_t)r*ldk + k0 + ldr_c*8);
                CPA16(wb + off, Bb + (size_t)r*ldk + k0 + ldr_c*8);
            }
            CPA_COMMIT();
        }

        uint32_t sa = sbase + STG_A(stage);
        uint32_t sb = sbase + STG_B(stage);
#pragma unroll
        for (int ks=0; ks<4; ks++){
            uint32_t af[4][4], bf[2][4];
#pragma unroll
            for (int mt=0;mt<4;mt++){
                int row = lA_row + mt*16;
                uint32_t off = row*128 + ks*32 + lA_kb;
                off ^= (off>>3)&0x70;
                LDSM4(af[mt][0],af[mt][1],af[mt][2],af[mt][3], sa + off);
            }
#pragma unroll
            for (int bt=0;bt<2;bt++){
                int row = lB_row + bt*16;
                uint32_t off = row*128 + ks*32 + lB_kb;
                off ^= (off>>3)&0x70;
                LDSM4(bf[bt][0],bf[bt][1],bf[bt][2],bf[bt][3], sb + off);
            }
#pragma unroll
            for (int mt=0;mt<4;mt++)
#pragma unroll
              for (int nt=0;nt<4;nt++){
                  uint32_t b0 = bf[nt>>1][(nt&1)*2];
                  uint32_t b1 = bf[nt>>1][(nt&1)*2+1];
                  MMA16816(acc[mt][nt], af[mt][0],af[mt][1],af[mt][2],af[mt][3], b0,b1);
              }
        }

        stage = (stage + 1 == 3) ? 0 : stage + 1;
        wstage = (wstage + 1 == 3) ? 0 : wstage + 1;
    }
    __syncthreads();

    const int grp = lane >> 2;
    const int thc = (lane & 3) * 2;
#pragma unroll
    for (int mt=0;mt<4;mt++){
#pragma unroll
        for (int half=0; half<2; half++){
            int grow = rowBase + warp_m*64 + mt*16 + grp + half*8;
            if (grow >= ROWS) continue;
#pragma unroll
            for (int nt=0;nt<4;nt++){
                float v0 = acc[mt][nt][half*2+0];
                float v1 = acc[mt][nt][half*2+1];
                int gcol = colBase + warp_n*32 + nt*8 + thc;
                if (epi == 0){
                    float2* p = (float2*)(outf + (size_t)grow*ldo + gcol);
                    *p = make_float2(v0, v1);
                } else if (epi == 1){
                    float2* p = (float2*)(outf + (size_t)grow*EMB + gcol);
                    float2 x = *p;
                    x.x += v0; x.y += v1;
                    *p = x;
                } else if (epi == 2){
                    float t0 = gelu_f(v0 + bias[gcol]);
                    float t1 = gelu_f(v1 + bias[gcol+1]);
                    __half2 hh; hh.x = __float2half_rn(t0); hh.y = __float2half_rn(t1);
                    *(__half2*)(outx1 + (size_t)grow*MLPD + gcol) = hh;
                } else {
                    float2* p = (float2*)(outf + (size_t)grow*EMB + gcol);
                    float2 x = *p;
                    x.x += v0 + bias[gcol]; x.y += v1 + bias[gcol+1];
                    *p = x;
                }
            }
        }
    }
}

// ---------------- fused attention, conservative SMEM (59.7 KB) --------------
#define FA_KS 0
#define FA_QS 12806
#define FA_FLOATS (FA_QS + 2112)
#define FA_SMEM (FA_FLOATS*4)

__global__ void __launch_bounds__(256) fattn(const float* __restrict__ qkv,
                                             __half* __restrict__ ox1)
{
    extern __shared__ float fsm[];
    float* Ks = fsm + FA_KS;
    float* Qs = fsm + FA_QS;
    float* Ps = fsm + FA_KS;
    float* Vs = fsm + FA_QS;
    const int tid = threadIdx.x, wid = tid >> 5, lane = tid & 31;
    const int bh = blockIdx.y;
    const int b = bh / NHEAD, h = bh - b*NHEAD;
    const int q0 = blockIdx.x * 32;
    const float* base = qkv + (size_t)b*SEQ*QKV3 + h*HDIM;

    for (int idx = tid; idx < SEQ*16; idx += 256){
        int r = idx >> 4, c4 = (idx & 15) << 2;
        float4 v = *(const float4*)(base + EMB + (size_t)r*QKV3 + c4);
        float* d = Ks + r*65 + c4;
        d[0]=v.x; d[1]=v.y; d[2]=v.z; d[3]=v.w;
    }
    for (int idx = tid; idx < 32*16; idx += 256){
        int r = idx >> 4, c4 = (idx & 15) << 2;
        int qr = q0 + r;
        float4 v = make_float4(0.f,0.f,0.f,0.f);
        if (qr < SEQ) v = *(const float4*)(base + (size_t)qr*QKV3 + c4);
        float* d = Qs + r*65 + c4;
        d[0]=v.x; d[1]=v.y; d[2]=v.z; d[3]=v.w;
    }
    __syncthreads();

    float s[4][7];
#pragma unroll
    for (int r=0;r<4;r++)
#pragma unroll
      for (int kk=0;kk<7;kk++) s[r][kk]=0.f;

    for (int d0=0; d0<HDIM; d0+=4){
        float q[4][4], k[7][4];
#pragma unroll
        for (int r=0;r<4;r++){
            const float* qp = Qs + (wid*4+r)*65 + d0;
            q[r][0]=qp[0]; q[r][1]=qp[1]; q[r][2]=qp[2]; q[r][3]=qp[3];
        }
#pragma unroll
        for (int kk=0;kk<7;kk++){
            const float* kp = Ks + (lane+32*kk)*65 + d0;
            k[kk][0]=kp[0]; k[kk][1]=kp[1]; k[kk][2]=kp[2]; k[kk][3]=kp[3];
        }
#pragma unroll
        for (int r=0;r<4;r++)
#pragma unroll
          for (int kk=0;kk<7;kk++)
#pragma unroll
            for (int j=0;j<4;j++)
                s[r][kk] += q[r][j]*k[kk][j];
    }

    float invs[4];
#pragma unroll
    for (int r=0;r<4;r++){
        float mx = -1e30f;
#pragma unroll
        for (int kk=0;kk<7;kk++){
            int key = lane + 32*kk;
            s[r][kk] = (key < SEQ) ? s[r][kk]*0.125f : -1e30f;
            mx = fmaxf(mx, s[r][kk]);
        }
#pragma unroll
        for (int o=16;o;o>>=1) mx = fmaxf(mx, __shfl_xor_sync(0xffffffffu, mx, o));
        float sum = 0.f;
#pragma unroll
        for (int kk=0;kk<7;kk++){
            float p = __expf(s[r][kk]-mx);
            s[r][kk] = p; sum += p;
        }
#pragma unroll
        for (int o=16;o;o>>=1) sum += __shfl_xor_sync(0xffffffffu, sum, o);
        invs[r] = 1.f/sum;
    }

    __syncthreads();

#pragma unroll
    for (int r=0;r<4;r++){
#pragma unroll
        for (int kk=0;kk<7;kk++){
            int key = lane + 32*kk;
            if (key < SEQ) Ps[(wid*4+r)*200 + key] = s[r][kk];
        }
    }

    float o[4][2];
#pragma unroll
    for (int r=0;r<4;r++){ o[r][0]=0.f; o[r][1]=0.f; }

    for (int kt=0; kt<SEQ; kt+=32){
        int nrows = SEQ - kt; if (nrows > 32) nrows = 32;
        __syncthreads();
        for (int idx = tid; idx < nrows*16; idx += 256){
            int r = idx >> 4, c4 = (idx & 15) << 2;
            float4 v = *(const float4*)(base + 2*EMB + (size_t)(kt+r)*QKV3 + c4);
            float* d = Vs + r*66 + c4;
            d[0]=v.x; d[1]=v.y; d[2]=v.z; d[3]=v.w;
        }
        __syncthreads();
        for (int kl=0; kl<nrows; kl++){
            float2 vv = *(float2*)(Vs + kl*66 + lane*2);
#pragma unroll
            for (int r=0;r<4;r++){
                float p = Ps[(wid*4+r)*200 + kt + kl];
                o[r][0] += p*vv.x; o[r][1] += p*vv.y;
            }
        }
    }

#pragma unroll
    for (int r=0;r<4;r++){
        int qr = q0 + wid*4 + r;
        if (qr >= SEQ) continue;
        float v0 = o[r][0]*invs[r], v1 = o[r][1]*invs[r];
        __half2 hh; hh.x = __float2half_rn(v0); hh.y = __float2half_rn(v1);
        __half* orow = ox1 + ((size_t)b*SEQ + qr)*EMB;
        int col = h*HDIM + lane*2;
        *(__half2*)(orow + col) = hh;
    }
}

// ---------------- weight convert: (L,K,N) fp32 -> (L,N,K) fp16 --------------
__global__ void wconv(const float* __restrict__ src, __half* __restrict__ dst,
                      int K, int N)
{
    int l = blockIdx.z;
    src += (size_t)l*K*N;
    dst += (size_t)l*N*K;
    __shared__ float sm[32][33];
    int k0 = blockIdx.x*32, n0 = blockIdx.y*32;
#pragma unroll
    for (int i=0;i<4;i++){
        int k = k0 + threadIdx.y + i*8;
        sm[threadIdx.y + i*8][threadIdx.x] = src[(size_t)k*N + n0 + threadIdx.x];
    }
    __syncthreads();
#pragma unroll
    for (int i=0;i<4;i++){
        int n = n0 + threadIdx.y + i*8;
        int k = k0 + threadIdx.x;
        float v = sm[threadIdx.x][threadIdx.y + i*8];
        dst[(size_t)n*K + k] = __float2half_rn(v);
    }
}

// ---------------- patch-embed GEMM (fp32) -----------------------------------
__global__ __launch_bounds__(256,2) void patch_gemm(
    const float* __restrict__ img, const float* __restrict__ Bw,
    const float* __restrict__ pbias, const float* __restrict__ pos,
    float* __restrict__ X)
{
    __shared__ float As[16][132];
    __shared__ float Bs[16][132];
    const int tid = threadIdx.x;
    const int rowBase = blockIdx.y * 128;
    const int colBase = blockIdx.x * 128;
    const int ty = tid >> 4, tx = tid & 15;

    float acc[2][2][4][4];
#pragma unroll
    for (int a=0;a<2;a++)
#pragma unroll
      for (int b=0;b<2;b++)
#pragma unroll
        for (int i=0;i<4;i++)
#pragma unroll
          for (int j=0;j<4;j++) acc[a][b][i][j]=0.f;

    for (int k0 = 0; k0 < EMB; k0 += 16) {
#pragma unroll
        for (int i=0;i<2;i++){
            int idx = tid + i*256;
            int r = idx >> 2;
            int c4 = (idx & 3) << 2;
            int gr = rowBase + r;
            int gk = k0 + c4;
            int b  = gr / NPATCH;
            int n  = gr - b*NPATCH;
            int pr = n / 14, pc = n - pr*14;
            int ch = gk >> 8;
            int py = (gk >> 4) & 15;
            int px = gk & 15;
            const float* src = img + ((((size_t)(b*3+ch))*224 + pr*16+py)*224 + pc*16 + px);
            float4 v = *(const float4*)src;
            As[c4+0][r]=v.x; As[c4+1][r]=v.y; As[c4+2][r]=v.z; As[c4+3][r]=v.w;
        }
#pragma unroll
        for (int i=0;i<2;i++){
            int idx = tid + i*256;
            int r = idx >> 5;
            int c4 = (idx & 31) << 2;
            *(float4*)&Bs[r][c4] = *(const float4*)(Bw + (size_t)(k0+r)*EMB + colBase + c4);
        }
        __syncthreads();
#pragma unroll
        for (int k=0;k<16;k++){
            float av[2][4], bv[2][4];
            *(float4*)&av[0][0] = *(const float4*)&As[k][ty*4];
            *(float4*)&av[1][0] = *(const float4*)&As[k][ty*4 + 64];
            *(float4*)&bv[0][0] = *(const float4*)&Bs[k][tx*4];
            *(float4*)&bv[1][0] = *(const float4*)&Bs[k][tx*4 + 64];
#pragma unroll
            for (int a=0;a<2;a++)
#pragma unroll
              for (int i=0;i<4;i++)
#pragma unroll
                for (int b=0;b<2;b++)
#pragma unroll
                  for (int j=0;j<4;j++)
                    acc[a][b][i][j] += av[a][i]*bv[b][j];
        }
        __syncthreads();
    }

#pragma unroll
    for (int a=0;a<2;a++){
#pragma unroll
        for (int b=0;b<2;b++){
            int r0 = rowBase + ty*4 + a*64;
            int c0 = colBase + tx*4 + b*64;
#pragma unroll
            for (int i=0;i<4;i++){
                int r = r0 + i;
                int bb = r / NPATCH;
                int n  = r - bb*NPATCH;
                float* Xrow = X + ((size_t)(bb*SEQ) + 1 + n)*EMB + c0;
                const float* prow = pos + (size_t)(1+n)*EMB + c0;
#pragma unroll
                for (int j=0;j<4;j++)
                    Xrow[j] = acc[a][b][i][j] + pbias[c0+j] + prow[j];
            }
        }
    }
}

__global__ void cls_init(const float* __restrict__ cls, const float* __restrict__ pos,
                         float* __restrict__ X)
{
    int idx = blockIdx.x*256 + threadIdx.x;
    if (idx >= BATCH*EMB) return;
    int b = idx / EMB, e = idx - b*EMB;
    X[(size_t)b*SEQ*EMB + e] = cls[e] + pos[e];
}

// ---------------- layernorm -> fp16 -----------------------------------------
__global__ void ln_x1(const float* __restrict__ in, __half* __restrict__ out)
{
    int row = blockIdx.x;
    const float* p = in + (size_t)row*EMB;
    int t = threadIdx.x;
    float v[3]; float s=0.f, s2=0.f;
#pragma unroll
    for (int i=0;i<3;i++){ v[i]=p[t + i*256]; s+=v[i]; s2+=v[i]*v[i]; }
    __shared__ float sh[2][8];
#pragma unroll
    for (int o=16;o;o>>=1){ s += __shfl_xor_sync(0xffffffffu,s,o); s2 += __shfl_xor_sync(0xffffffffu,s2,o); }
    if ((t&31)==0){ sh[0][t>>5]=s; sh[1][t>>5]=s2; }
    __syncthreads();
    if (t < 32){
        s  = (t<8)? sh[0][t] : 0.f;
        s2 = (t<8)? sh[1][t] : 0.f;
#pragma unroll
        for (int o=4;o;o>>=1){ s += __shfl_xor_sync(0xffffffffu,s,o); s2 += __shfl_xor_sync(0xffffffffu,s2,o); }
        if (t==0){ sh[0][0]=s; sh[1][0]=s2; }
    }
    __syncthreads();
    float mu  = sh[0][0]*(1.f/EMB);
    float var = sh[1][0]*(1.f/EMB) - mu*mu;
    float inv = rsqrtf(var + 1e-5f);
    __half* q = out + (size_t)row*EMB;
#pragma unroll
    for (int i=0;i<3;i++){
        int e = t + i*256;
        q[e] = __float2half_rn((v[i]-mu)*inv);
    }
}

__global__ void lnfinal_k(const float* __restrict__ X, const float* __restrict__ g,
                          const float* __restrict__ bta, float* __restrict__ out)
{
    int b = blockIdx.x;
    const float* p = X + (size_t)b*SEQ*EMB;
    int t = threadIdx.x;
    float v[3]; float s=0.f, s2=0.f;
#pragma unroll
    for (int i=0;i<3;i++){ v[i]=p[t + i*256]; s+=v[i]; s2+=v[i]*v[i]; }
    __shared__ float sh[2][8];
#pragma unroll
    for (int o=16;o;o>>=1){ s += __shfl_xor_sync(0xffffffffu,s,o); s2 += __shfl_xor_sync(0xffffffffu,s2,o); }
    if ((t&31)==0){ sh[0][t>>5]=s; sh[1][t>>5]=s2; }
    __syncthreads();
    if (t < 32){
        s  = (t<8)? sh[0][t] : 0.f;
        s2 = (t<8)? sh[1][t] : 0.f;
#pragma unroll
        for (int o=4;o;o>>=1){ s += __shfl_xor_sync(0xffffffffu,s,o); s2 += __shfl_xor_sync(0xffffffffu,s2,o); }
        if (t==0){ sh[0][0]=s; sh[1][0]=s2; }
    }
    __syncthreads();
    float mu  = sh[0][0]*(1.f/EMB);
    float var = sh[1][0]*(1.f/EMB) - mu*mu;
    float inv = rsqrtf(var + 1e-5f);
#pragma unroll
    for (int i=0;i<3;i++){
        int e = t + i*256;
        out[(size_t)b*EMB + e] = (v[i]-mu)*inv*g[e] + bta[e];
    }
}

__global__ void head_k(const float* __restrict__ cls, const float* __restrict__ hw,
                       const float* __restrict__ hb, float* __restrict__ out)
{
    int t = threadIdx.x;
    if (t >= BATCH*10) return;
    int b = t/10, c = t - b*10;
    float s = __ldg(hb + c);
    const float* crow = cls + (size_t)b*EMB;
    for (int e=0;e<EMB;e++) s += crow[e]*__ldg(hw + (size_t)e*10 + c);
    out[t] = s;
}

// ---------------- launch ----------------------------------------------------
extern "C" void kernel_launch(void* const* d_in, const int* in_sizes, int n_in,
                              void* d_out, int out_size)
{
    (void)in_sizes; (void)n_in; (void)out_size;
    const float* img     = (const float*)d_in[0];
    const float* patch_w = (const float*)d_in[1];
    const float* patch_b = (const float*)d_in[2];
    const float* cls_tok = (const float*)d_in[3];
    const float* pos_emb = (const float*)d_in[4];
    const float* qkv_w   = (const float*)d_in[5];
    const float* fc_w    = (const float*)d_in[6];
    const float* mlp_w1  = (const float*)d_in[7];
    const float* mlp_b1  = (const float*)d_in[8];
    const float* mlp_w2  = (const float*)d_in[9];
    const float* mlp_b2  = (const float*)d_in[10];
    const float* ln_g    = (const float*)d_in[11];
    const float* ln_b    = (const float*)d_in[12];
    const float* head_w  = (const float*)d_in[13];
    const float* head_b  = (const float*)d_in[14];
    float* out = (float*)d_out;

    static float *x=nullptr,*qkv=nullptr,*clsb=nullptr;
    static __half *hx1=nullptr,*ox1=nullptr,*mx1=nullptr,*wq=nullptr,*wf=nullptr,*w1=nullptr,*w2=nullptr;
    if (!x){
        cudaGetSymbolAddress((void**)&x,    g_x);
        cudaGetSymbolAddress((void**)&qkv,  g_qkv);
        cudaGetSymbolAddress((void**)&clsb, g_cls);
        cudaGetSymbolAddress((void**)&hx1,  g_hx1);
        cudaGetSymbolAddress((void**)&ox1,  g_ox1);
        cudaGetSymbolAddress((void**)&mx1,  g_mx1);
        cudaGetSymbolAddress((void**)&wq,   g_wq);
        cudaGetSymbolAddress((void**)&wf,   g_wf);
        cudaGetSymbolAddress((void**)&w1,   g_w1);
        cudaGetSymbolAddress((void**)&w2,   g_w2);
        cudaFuncSetAttribute(tgemm, cudaFuncAttributeMaxDynamicSharedMemorySize, SM_TOTAL);
        cudaFuncSetAttribute(fattn, cudaFuncAttributeMaxDynamicSharedMemorySize, FA_SMEM);
    }

    // weight convert (fp16 transpose), all layers
    wconv<<<dim3(EMB/32,  QKV3/32, NLAYER), dim3(32,8)>>>(qkv_w,  wq, EMB,  QKV3);
    wconv<<<dim3(EMB/32,  EMB/32,  NLAYER), dim3(32,8)>>>(fc_w,   wf, EMB,  EMB);
    wconv<<<dim3(EMB/32,  MLPD/32, NLAYER), dim3(32,8)>>>(mlp_w1, w1, EMB,  MLPD);
    wconv<<<dim3(MLPD/32, EMB/32,  NLAYER), dim3(32,8)>>>(mlp_w2, w2, MLPD, EMB);

    patch_gemm<<<dim3(6,49),256>>>(img, patch_w, patch_b, pos_emb, x);
    cls_init<<<(BATCH*EMB+255)/256,256>>>(cls_tok, pos_emb, x);

    for (int l=0; l<NLAYER; l++){
        ln_x1<<<ROWS,256>>>(x, hx1);
        tgemm<<<dim3(QKV3/128, ROWS_PAD/128), 256, SM_TOTAL>>>(
            hx1, wq + (size_t)l*QKV3*EMB, EMB, 12, qkv, QKV3, nullptr, nullptr, 0);
        fattn<<<dim3(7, BHEADS), 256, FA_SMEM>>>(qkv, ox1);
        tgemm<<<dim3(EMB/128, ROWS_PAD/128), 256, SM_TOTAL>>>(
            ox1, wf + (size_t)l*EMB*EMB, EMB, 12, x, EMB, nullptr, nullptr, 1);
        ln_x1<<<ROWS,256>>>(x, hx1);
        tgemm<<<dim3(MLPD/128, ROWS_PAD/128), 256, SM_TOTAL>>>(
            hx1, w1 + (size_t)l*MLPD*EMB, EMB, 12, nullptr, 0,
            mlp_b1 + (size_t)l*MLPD, mx1, 2);
        tgemm<<<dim3(EMB/128, ROWS_PAD/128), 256, SM_TOTAL>>>(
            mx1, w2 + (size_t)l*EMB*MLPD, MLPD, 48, x, EMB,
            mlp_b2 + (size_t)l*EMB, nullptr, 3);
    }

    lnfinal_k<<<BATCH,256>>>(x, ln_g, ln_b, clsb);
    head_k<<<1,512>>>(clsb, head_w, head_b, out);
}